// round 10
// baseline (speedup 1.0000x reference)
#include <cuda_runtime.h>
#include <math.h>
#include <stdint.h>

#define T_   256
#define B_   64
#define I_   256
#define H_   512
#define C_   64
#define G4H  2048
#define BH   (B_*H_)      // 32768
#define NCTA 136
#define NGEMM 128
#define NGRP_CTA 34       // per-group arrivals: 32 GEMM + 2 attention
#define NSYNC (256*4*32)  // step x group, 128B apart

// lstm smem (floats)
#define W2S 68
#define H2S 36
#define W2_ELE (512 * W2S)        // 34816
#define H2_ELE (512 * H2S)        // 18432
#define PT_ELE (4 * 1024)         // 4096
#define SMEM_FLOATS (W2_ELE + H2_ELE + PT_ELE)
#define SMEM_BYTES  (SMEM_FLOATS * 4)   // 229376 B

// ---------------- static device scratch ----------------
__device__ float    d_G[(size_t)T_ * B_ * G4H];
__device__ float    d_hn[(size_t)(T_ + 1) * BH];    // LSTM part: hn[t+1]=hn(step t)
__device__ float    d_msS[(size_t)(T_ + 1) * BH];   // m_t part: msS[t+1]=m_t(step t)
__device__ unsigned d_bar[NSYNC];
// mem[t] = d_hn[t] + d_msS[t]

__device__ __forceinline__ float sigf(float x) { return 1.f / (1.f + __expf(-x)); }

__device__ __forceinline__ void upk2(unsigned long long v, float& x, float& y) {
    asm("mov.b64 {%0, %1}, %2;" : "=f"(x), "=f"(y) : "l"(v));
}
__device__ __forceinline__ unsigned long long fma2(unsigned long long a,
                                                   unsigned long long b,
                                                   unsigned long long c) {
    unsigned long long d;
    asm("fma.rn.f32x2 %0, %1, %2, %3;" : "=l"(d) : "l"(a), "l"(b), "l"(c));
    return d;
}

// per-GROUP release/acquire barrier; fence+arrive+spin by thread 0 only.
// Each (step, group) slot sits on its own 128B line.
__device__ __forceinline__ void gsync(int step, int grp, unsigned nct) {
    __syncthreads();
    if (threadIdx.x == 0) {
        unsigned* slot = &d_bar[(step * 4 + grp) * 32];
        __threadfence();
        atomicAdd(slot, 1u);
        while (*((volatile unsigned*)slot) < nct) { }
        __threadfence();
    }
    __syncthreads();
}

__global__ void noop_kernel() {}

// ---------------- reset ----------------
__global__ void reset_kernel() {
    int id = blockIdx.x * blockDim.x + threadIdx.x;   // 32768 threads
    d_hn[id] = 0.f;     // row 0
    d_msS[id] = 0.f;    // row 0
    d_bar[id] = 0u;     // NSYNC == 32768 exactly
}

// ---------------- K1: G = x @ W_ih^T + (b_ih + b_hh) ----------------
__global__ void __launch_bounds__(256) gemm_ih_kernel(const float* __restrict__ X,
                                                      const float* __restrict__ Wih,
                                                      const float* __restrict__ bih,
                                                      const float* __restrict__ bhh) {
    __shared__ __align__(16) float a_s[16][64];
    __shared__ __align__(16) float b_s[16][64];
    int tx = threadIdx.x;
    int m0 = blockIdx.y * 64, n0 = blockIdx.x * 64;
    int tm = tx & 15, tn = tx >> 4;
    float acc[4][4];
#pragma unroll
    for (int r = 0; r < 4; r++)
#pragma unroll
        for (int c = 0; c < 4; c++) acc[r][c] = 0.f;

    int row = tx >> 2, qd = tx & 3;
    for (int k0 = 0; k0 < I_; k0 += 16) {
        float4 av = *(const float4*)(X + (size_t)(m0 + row) * I_ + k0 + qd * 4);
        float4 bv = *(const float4*)(Wih + (size_t)(n0 + row) * I_ + k0 + qd * 4);
        a_s[qd*4+0][row] = av.x; a_s[qd*4+1][row] = av.y; a_s[qd*4+2][row] = av.z; a_s[qd*4+3][row] = av.w;
        b_s[qd*4+0][row] = bv.x; b_s[qd*4+1][row] = bv.y; b_s[qd*4+2][row] = bv.z; b_s[qd*4+3][row] = bv.w;
        __syncthreads();
#pragma unroll
        for (int k = 0; k < 16; k++) {
            float4 a = *(const float4*)&a_s[k][tm * 4];
            float4 b = *(const float4*)&b_s[k][tn * 4];
            acc[0][0] = fmaf(a.x, b.x, acc[0][0]); acc[0][1] = fmaf(a.x, b.y, acc[0][1]);
            acc[0][2] = fmaf(a.x, b.z, acc[0][2]); acc[0][3] = fmaf(a.x, b.w, acc[0][3]);
            acc[1][0] = fmaf(a.y, b.x, acc[1][0]); acc[1][1] = fmaf(a.y, b.y, acc[1][1]);
            acc[1][2] = fmaf(a.y, b.z, acc[1][2]); acc[1][3] = fmaf(a.y, b.w, acc[1][3]);
            acc[2][0] = fmaf(a.z, b.x, acc[2][0]); acc[2][1] = fmaf(a.z, b.y, acc[2][1]);
            acc[2][2] = fmaf(a.z, b.z, acc[2][2]); acc[2][3] = fmaf(a.z, b.w, acc[2][3]);
            acc[3][0] = fmaf(a.w, b.x, acc[3][0]); acc[3][1] = fmaf(a.w, b.y, acc[3][1]);
            acc[3][2] = fmaf(a.w, b.z, acc[3][2]); acc[3][3] = fmaf(a.w, b.w, acc[3][3]);
        }
        __syncthreads();
    }
    float bias[4];
#pragma unroll
    for (int c = 0; c < 4; c++) {
        int n = n0 + tn * 4 + c;
        bias[c] = __ldg(bih + n) + __ldg(bhh + n);
    }
#pragma unroll
    for (int r = 0; r < 4; r++) {
        size_t m = (size_t)(m0 + tm * 4 + r);
        float4 o;
        o.x = acc[r][0] + bias[0]; o.y = acc[r][1] + bias[1];
        o.z = acc[r][2] + bias[2]; o.w = acc[r][3] + bias[3];
        *(float4*)(d_G + m * G4H + n0 + tn * 4) = o;
    }
}

// ---------------- K2: fused persistent recurrent kernel ----------------
// 4 INDEPENDENT groups (bg = 16 batches): 32 GEMM CTAs + 2 attention CTAs each,
// own 34-arrival barrier per step. No cross-group data flow.
__global__ void __launch_bounds__(256, 1) lstm_persistent(const float* __restrict__ W_hh,
                                                          const float* __restrict__ w_t) {
    extern __shared__ __align__(16) float smem[];
    float* w2f  = smem;                     // [k][2*jp] pairs, stride W2S
    float* h2f  = smem + W2_ELE;            // [k][2*b] dup'd pairs, stride H2S
    float* p_sm = smem + W2_ELE + H2_ELE;   // partials [kg][b][j]

    int g = blockIdx.x, tx = threadIdx.x;
    int wrp = tx >> 5, lane = tx & 31;

    if (g < NGEMM) {
        int jg = g >> 2, bg = g & 3;
        int h0 = jg * 16;

        // ---- stage W pairs once ----
#pragma unroll
        for (int q2 = 0; q2 < 64; q2++) {
            int idx = q2 * 256 + tx;             // [0, 16384)
            int jp = idx >> 9, k = idx & 511;
            int jj0 = 2 * jp, jj1 = 2 * jp + 1;
            int r0 = (jj0 >> 4) * H_ + h0 + (jj0 & 15);
            int r1 = (jj1 >> 4) * H_ + h0 + (jj1 & 15);
            float2 v;
            v.x = __ldg(W_hh + (size_t)r0 * H_ + k);
            v.y = __ldg(W_hh + (size_t)r1 * H_ + k);
            *(float2*)&w2f[k * W2S + 2 * jp] = v;
        }
        __syncthreads();

        // k-loop mapping: 8 warps = 4 k-groups x 2 b-halves
        int kg = wrp & 3, half = wrp >> 2;
        int bq = lane >> 3, jq = lane & 7;
        int b0 = half * 8 + bq * 2;

        // cell mapping: one (b,h) per thread
        int bl = tx >> 4, hi = tx & 15;
        const float* gsrc = d_G + ((size_t)bg * 16 + bl) * G4H + h0 + hi;
        float cstate = 0.f;

        for (int i = 0; i < T_; ++i) {
            // ---- prefetch input-proj gates for this thread's cell ----
            const float* gs = gsrc + (size_t)i * B_ * G4H;
            float gp0 = __ldcg(gs);
            float gp1 = __ldcg(gs + 512);
            float gp2 = __ldcg(gs + 1024);
            float gp3 = __ldcg(gs + 1536);

            // ---- stage h2 dup'd: h = hn[i] + msS[i] ----
            const float* hnp = d_hn  + (size_t)i * BH + (size_t)bg * 16 * H_;
            const float* msp = d_msS + (size_t)i * BH + (size_t)bg * 16 * H_;
#pragma unroll
            for (int q2 = 0; q2 < 8; q2++) {
                int it = q2 * 256 + tx;          // [0,2048) float4s
                int b = it & 15, kq = it >> 4;   // kq in [0,128)
                float4 a = __ldcg((const float4*)(hnp + (size_t)b * H_ + kq * 4));
                float4 c = __ldcg((const float4*)(msp + (size_t)b * H_ + kq * 4));
                a.x += c.x; a.y += c.y; a.z += c.z; a.w += c.w;
                *(float2*)&h2f[(4*kq+0) * H2S + 2*b] = make_float2(a.x, a.x);
                *(float2*)&h2f[(4*kq+1) * H2S + 2*b] = make_float2(a.y, a.y);
                *(float2*)&h2f[(4*kq+2) * H2S + 2*b] = make_float2(a.z, a.z);
                *(float2*)&h2f[(4*kq+3) * H2S + 2*b] = make_float2(a.w, a.w);
            }
            __syncthreads();

            // ---- FFMA2 k-loop: 128 k per warp, 2b x 8j per lane ----
            {
                unsigned long long a0=0,a1=0,a2=0,a3=0,a4=0,a5=0,a6=0,a7=0;
                const float* wp = w2f + (size_t)(kg * 128) * W2S + 4 * jq;
                const float* hp = h2f + (size_t)(kg * 128) * H2S + 2 * b0;
#pragma unroll 8
                for (int k = 0; k < 128; k++) {
                    ulonglong2 hv = *(const ulonglong2*)hp;        // (h0,h0),(h1,h1)
                    ulonglong2 wA = *(const ulonglong2*)wp;        // jpairs 2jq, 2jq+1
                    ulonglong2 wB = *(const ulonglong2*)(wp + 32); // jpairs 16+2jq, 17+2jq
                    a0 = fma2(hv.x, wA.x, a0); a1 = fma2(hv.x, wA.y, a1);
                    a2 = fma2(hv.x, wB.x, a2); a3 = fma2(hv.x, wB.y, a3);
                    a4 = fma2(hv.y, wA.x, a4); a5 = fma2(hv.y, wA.y, a5);
                    a6 = fma2(hv.y, wB.x, a6); a7 = fma2(hv.y, wB.y, a7);
                    wp += W2S; hp += H2S;
                }
                float* pb = p_sm + kg * 1024 + b0 * 64 + 4 * jq;
                float4 o;
                upk2(a0, o.x, o.y); upk2(a1, o.z, o.w); *(float4*)pb = o;
                upk2(a2, o.x, o.y); upk2(a3, o.z, o.w); *(float4*)(pb + 32) = o;
                upk2(a4, o.x, o.y); upk2(a5, o.z, o.w); *(float4*)(pb + 64) = o;
                upk2(a6, o.x, o.y); upk2(a7, o.z, o.w); *(float4*)(pb + 96) = o;
            }
            __syncthreads();

            // ---- cell: reduce 4 partials + input proj, LSTM -> d_hn ----
            {
                int base = bl * 64 + hi;
                float gi = gp0, gf = gp1, gg = gp2, go = gp3;
#pragma unroll
                for (int kk = 0; kk < 4; kk++) {
                    const float* pp = p_sm + kk * 1024 + base;
                    gi += pp[0];
                    gf += pp[16];
                    gg += pp[32];
                    go += pp[48];
                }
                size_t off = (size_t)(bg * 16 + bl) * H_ + h0 + hi;
                float cn = sigf(gf) * cstate + sigf(gi) * tanhf(gg);
                float hn = sigf(go) * tanhf(cn);
                cstate = cn;
                d_hn[(size_t)(i + 1) * BH + off] = hn;
            }

            gsync(i, bg, NGRP_CTA);
        }
    } else {
        // ---------------- attention CTAs: warp per batch, group (g-128)>>1 ----------------
        int a = g - NGEMM;                 // 0..7
        int grp = a >> 1;                  // batch group bg
        int b = a * 8 + wrp;               // this warp's batch
        float4 wt2r[4];
#pragma unroll
        for (int q = 0; q < 4; q++)
            wt2r[q] = *(const float4*)(w_t + H_ + q * 128 + lane * 4);

        float v[8];                        // master scores: v[r] = score(t = lane + 32r)
#pragma unroll
        for (int r = 0; r < 8; r++) v[r] = -INFINITY;

        const float* hnb = d_hn  + (size_t)b * H_;
        const float* msb = d_msS + (size_t)b * H_;

        for (int i = 0; i < T_; ++i) {
            // ---- s_new for row t=i from mem[i] = hn[i]+msS[i] (coalesced) ----
            float part = 0.f;
#pragma unroll
            for (int q = 0; q < 4; q++) {
                const float4 aa = __ldcg((const float4*)(hnb + (size_t)i * BH + q * 128 + lane * 4));
                const float4 cc = __ldcg((const float4*)(msb + (size_t)i * BH + q * 128 + lane * 4));
                part += tanhf(aa.x + cc.x) * wt2r[q].x;
                part += tanhf(aa.y + cc.y) * wt2r[q].y;
                part += tanhf(aa.z + cc.z) * wt2r[q].z;
                part += tanhf(aa.w + cc.w) * wt2r[q].w;
            }
#pragma unroll
            for (int o = 16; o > 0; o >>= 1) part += __shfl_xor_sync(0xffffffffu, part, o);
            {
                int rr = i >> 5, ll = i & 31;
#pragma unroll
                for (int r = 0; r < 8; r++)
                    if (r == rr && lane == ll) v[r] = part;
            }

            int n = i + 1;
            float mn = INFINITY;
#pragma unroll
            for (int r = 0; r < 8; r++) {
                int t = lane + 32 * r;
                if (t < n) mn = fminf(mn, v[r]);
            }
#pragma unroll
            for (int o = 16; o > 0; o >>= 1) mn = fminf(mn, __shfl_xor_sync(0xffffffffu, mn, o));

            float w[8];
#pragma unroll
            for (int r = 0; r < 8; r++) w[r] = v[r];
            float topv[5]; int topt[5];
#pragma unroll
            for (int k5 = 0; k5 < 5; k5++) {
                float bv = -INFINITY; int bt = 1 << 30;
#pragma unroll
                for (int r = 0; r < 8; r++) {
                    int t = lane + 32 * r;
                    if (w[r] > bv) { bv = w[r]; bt = t; }
                }
#pragma unroll
                for (int o = 16; o > 0; o >>= 1) {
                    float ov = __shfl_xor_sync(0xffffffffu, bv, o);
                    int   ot = __shfl_xor_sync(0xffffffffu, bt, o);
                    if (ov > bv || (ov == bv && ot < bt)) { bv = ov; bt = ot; }
                }
                topv[k5] = bv; topt[k5] = bt;
                int rr = bt >> 5;
                if ((bt & 31) == lane && rr >= 0 && rr < 8) w[rr] = -INFINITY;
            }
            float delta = ((n <= 5) ? mn : topv[4]) + 1e-7f;
            float wk[5]; float sum = 0.f;
#pragma unroll
            for (int k5 = 0; k5 < 5; k5++) { wk[k5] = fmaxf(topv[k5] - delta, 0.f); sum += wk[k5]; }
            float inv = 1.f / (sum + 1e-7f);

            // gather m_t = sum wk * (hn[t'] + msS[t']) — coalesced float4
            float4 acc4[4];
#pragma unroll
            for (int q = 0; q < 4; q++) acc4[q] = make_float4(0.f, 0.f, 0.f, 0.f);
#pragma unroll
            for (int k5 = 0; k5 < 5; k5++) {
                float wv = wk[k5] * inv;
                if (wv > 0.f) {
                    size_t rb = (size_t)topt[k5] * BH;
#pragma unroll
                    for (int q = 0; q < 4; q++) {
                        const float4 aa = __ldg((const float4*)(hnb + rb + q * 128 + lane * 4));
                        const float4 cc = __ldg((const float4*)(msb + rb + q * 128 + lane * 4));
                        acc4[q].x = fmaf(wv, aa.x + cc.x, acc4[q].x);
                        acc4[q].y = fmaf(wv, aa.y + cc.y, acc4[q].y);
                        acc4[q].z = fmaf(wv, aa.z + cc.z, acc4[q].z);
                        acc4[q].w = fmaf(wv, aa.w + cc.w, acc4[q].w);
                    }
                }
            }
            float* mw = d_msS + (size_t)(i + 1) * BH + (size_t)b * H_;
#pragma unroll
            for (int q = 0; q < 4; q++)
                *(float4*)(mw + q * 128 + lane * 4) = acc4[q];

            gsync(i, grp, NGRP_CTA);
        }
    }
}

// ---------------- K3: out = [h_seq | m_seq] @ fc_w^T + fc_b ----------------
__global__ void __launch_bounds__(256) fc_final_kernel(const float* __restrict__ fcw,
                                                       const float* __restrict__ fcb,
                                                       float* __restrict__ out) {
    __shared__ __align__(16) float a_s[16][64];
    __shared__ __align__(16) float b_s[16][64];
    int tx = threadIdx.x;
    int m0 = blockIdx.x * 64;
    int tm = tx & 15, tn = tx >> 4;
    float acc[4][4];
#pragma unroll
    for (int r = 0; r < 4; r++)
#pragma unroll
        for (int c = 0; c < 4; c++) acc[r][c] = 0.f;

    int row = tx >> 2, qd = tx & 3;
    int m = m0 + row, t = m >> 6, b = m & 63;
    for (int k0 = 0; k0 < 2 * H_; k0 += 16) {
        int k = k0 + qd * 4;
        float4 av;
        if (k < H_) {
            size_t off = ((size_t)(t + 1) * B_ + b) * H_ + k;
            float4 a = *(const float4*)(d_hn + off);
            float4 c = *(const float4*)(d_msS + off);
            av = make_float4(a.x + c.x, a.y + c.y, a.z + c.z, a.w + c.w);
        } else {
            av = *(const float4*)(d_msS + ((size_t)(t + 1) * B_ + b) * H_ + (k - H_));
        }
        float4 bv = *(const float4*)(fcw + (size_t)row * (2 * H_) + k);
        a_s[qd*4+0][row] = av.x; a_s[qd*4+1][row] = av.y; a_s[qd*4+2][row] = av.z; a_s[qd*4+3][row] = av.w;
        b_s[qd*4+0][row] = bv.x; b_s[qd*4+1][row] = bv.y; b_s[qd*4+2][row] = bv.z; b_s[qd*4+3][row] = bv.w;
        __syncthreads();
#pragma unroll
        for (int k2 = 0; k2 < 16; k2++) {
            float4 a = *(const float4*)&a_s[k2][tm * 4];
            float4 bb = *(const float4*)&b_s[k2][tn * 4];
            acc[0][0] = fmaf(a.x, bb.x, acc[0][0]); acc[0][1] = fmaf(a.x, bb.y, acc[0][1]);
            acc[0][2] = fmaf(a.x, bb.z, acc[0][2]); acc[0][3] = fmaf(a.x, bb.w, acc[0][3]);
            acc[1][0] = fmaf(a.y, bb.x, acc[1][0]); acc[1][1] = fmaf(a.y, bb.y, acc[1][1]);
            acc[1][2] = fmaf(a.y, bb.z, acc[1][2]); acc[1][3] = fmaf(a.y, bb.w, acc[1][3]);
            acc[2][0] = fmaf(a.z, bb.x, acc[2][0]); acc[2][1] = fmaf(a.z, bb.y, acc[2][1]);
            acc[2][2] = fmaf(a.z, bb.z, acc[2][2]); acc[2][3] = fmaf(a.z, bb.w, acc[2][3]);
            acc[3][0] = fmaf(a.w, bb.x, acc[3][0]); acc[3][1] = fmaf(a.w, bb.y, acc[3][1]);
            acc[3][2] = fmaf(a.w, bb.z, acc[3][2]); acc[3][3] = fmaf(a.w, bb.w, acc[3][3]);
        }
        __syncthreads();
    }
    float bias[4];
#pragma unroll
    for (int c = 0; c < 4; c++) bias[c] = __ldg(fcb + tn * 4 + c);
#pragma unroll
    for (int r = 0; r < 4; r++) {
        size_t mm = (size_t)(m0 + tm * 4 + r);
        float4 o;
        o.x = acc[r][0] + bias[0]; o.y = acc[r][1] + bias[1];
        o.z = acc[r][2] + bias[2]; o.w = acc[r][3] + bias[3];
        *(float4*)(out + mm * C_ + tn * 4) = o;
    }
}

// ---------------- launch ----------------
extern "C" void kernel_launch(void* const* d_in, const int* in_sizes, int n_in,
                              void* d_out, int out_size) {
    const float* x    = (const float*)d_in[0];
    const float* W_ih = (const float*)d_in[1];
    const float* W_hh = (const float*)d_in[2];
    const float* b_ih = (const float*)d_in[3];
    const float* b_hh = (const float*)d_in[4];
    const float* w_t  = (const float*)d_in[5];
    const float* fc_w = (const float*)d_in[6];
    const float* fc_b = (const float*)d_in[7];
    float* out = (float*)d_out;

    static int smem_set = 0;
    if (!smem_set) {
        cudaFuncSetAttribute(lstm_persistent,
                             cudaFuncAttributeMaxDynamicSharedMemorySize, SMEM_BYTES);
        smem_set = 1;
    }

    // ncu profiles launch #4 -> keep lstm_persistent there.
    reset_kernel<<<64, 512>>>();
    gemm_ih_kernel<<<dim3(G4H / 64, (T_ * B_) / 64), 256>>>(x, W_ih, b_ih, b_hh);
    noop_kernel<<<1, 1>>>();
    lstm_persistent<<<NCTA, 256, SMEM_BYTES>>>(W_hh, w_t);
    fc_final_kernel<<<(T_ * B_) / 64, 256>>>(fc_w, fc_b, out);
}

// round 11
// speedup vs baseline: 1.3817x; 1.3817x over previous
#include <cuda_runtime.h>
#include <math.h>
#include <stdint.h>

#define T_   256
#define B_   64
#define I_   256
#define H_   512
#define C_   64
#define G4H  2048
#define BH   (B_*H_)      // 32768
#define NCTA 136
#define NGEMM 128
#define NATT_CTA 8
#define NSYNC 256

// lstm smem (floats)
#define W2S 68
#define H2S 36
#define W2_ELE (512 * W2S)        // 34816
#define H2_ELE (512 * H2S)        // 18432
#define PT_ELE (4 * 1024)         // 4096
#define SMEM_FLOATS (W2_ELE + H2_ELE + PT_ELE)
#define SMEM_BYTES  (SMEM_FLOATS * 4)   // 229376 B

// ---------------- static device scratch ----------------
__device__ float    d_G[(size_t)T_ * B_ * G4H];
__device__ float    d_mem[(size_t)(T_ + 1) * BH];   // mem rows; mem[i+1] = h_out[i]
__device__ float    d_mseq[(size_t)T_ * BH];        // m_t per step
__device__ unsigned d_bar[NSYNC];
__device__ unsigned d_aflag[NSYNC];

__device__ __forceinline__ float sigf(float x) { return 1.f / (1.f + __expf(-x)); }

__device__ __forceinline__ void upk2(unsigned long long v, float& x, float& y) {
    asm("mov.b64 {%0, %1}, %2;" : "=f"(x), "=f"(y) : "l"(v));
}
__device__ __forceinline__ unsigned long long fma2(unsigned long long a,
                                                   unsigned long long b,
                                                   unsigned long long c) {
    unsigned long long d;
    asm("fma.rn.f32x2 %0, %1, %2, %3;" : "=l"(d) : "l"(a), "l"(b), "l"(c));
    return d;
}

// release/acquire grid barrier; fence+arrive+spin by thread 0 only
__device__ __forceinline__ void gsync(int slot, unsigned nct) {
    __syncthreads();
    if (threadIdx.x == 0) {
        __threadfence();
        atomicAdd(&d_bar[slot], 1u);
        while (*((volatile unsigned*)&d_bar[slot]) < nct) { }
        __threadfence();
    }
    __syncthreads();
}

__global__ void noop_kernel() {}

// ---------------- reset ----------------
__global__ void reset_kernel() {
    int id = blockIdx.x * blockDim.x + threadIdx.x;   // 32768 threads
    d_mem[id] = 0.f;                                   // row 0
    if (id < NSYNC) { d_bar[id] = 0u; d_aflag[id] = 0u; }
}

// ---------------- K1: G = x @ W_ih^T + (b_ih + b_hh), FFMA2 (R5 version) ----------------
#define A2_STRIDE 132
__global__ void __launch_bounds__(256) gemm_ih_kernel(const float* __restrict__ X,
                                                      const float* __restrict__ Wih,
                                                      const float* __restrict__ bih,
                                                      const float* __restrict__ bhh) {
    __shared__ __align__(16) float a2f[16 * A2_STRIDE];   // [k][m-dup]
    __shared__ __align__(16) float b_s[16][64];
    int tx = threadIdx.x;
    int m0 = blockIdx.y * 64, n0 = blockIdx.x * 64;
    int tm = tx & 15, tn = tx >> 4;
    unsigned long long acc[4][2];
#pragma unroll
    for (int r = 0; r < 4; r++) { acc[r][0] = 0ull; acc[r][1] = 0ull; }

    int row = tx >> 2, qd = tx & 3;
    for (int k0 = 0; k0 < I_; k0 += 16) {
        float4 av = *(const float4*)(X + (size_t)(m0 + row) * I_ + k0 + qd * 4);
        float4 bv = *(const float4*)(Wih + (size_t)(n0 + row) * I_ + k0 + qd * 4);
        *(float2*)&a2f[(qd*4+0) * A2_STRIDE + 2*row] = make_float2(av.x, av.x);
        *(float2*)&a2f[(qd*4+1) * A2_STRIDE + 2*row] = make_float2(av.y, av.y);
        *(float2*)&a2f[(qd*4+2) * A2_STRIDE + 2*row] = make_float2(av.z, av.z);
        *(float2*)&a2f[(qd*4+3) * A2_STRIDE + 2*row] = make_float2(av.w, av.w);
        b_s[qd*4+0][row] = bv.x; b_s[qd*4+1][row] = bv.y;
        b_s[qd*4+2][row] = bv.z; b_s[qd*4+3][row] = bv.w;
        __syncthreads();
#pragma unroll
        for (int k = 0; k < 16; k++) {
            ulonglong2 aA = *(const ulonglong2*)&a2f[k * A2_STRIDE + 8 * tm];
            ulonglong2 aB = *(const ulonglong2*)&a2f[k * A2_STRIDE + 8 * tm + 4];
            ulonglong2 bb = *(const ulonglong2*)&b_s[k][tn * 4];
            acc[0][0] = fma2(aA.x, bb.x, acc[0][0]); acc[0][1] = fma2(aA.x, bb.y, acc[0][1]);
            acc[1][0] = fma2(aA.y, bb.x, acc[1][0]); acc[1][1] = fma2(aA.y, bb.y, acc[1][1]);
            acc[2][0] = fma2(aB.x, bb.x, acc[2][0]); acc[2][1] = fma2(aB.x, bb.y, acc[2][1]);
            acc[3][0] = fma2(aB.y, bb.x, acc[3][0]); acc[3][1] = fma2(aB.y, bb.y, acc[3][1]);
        }
        __syncthreads();
    }
    float bias[4];
#pragma unroll
    for (int c = 0; c < 4; c++) {
        int n = n0 + tn * 4 + c;
        bias[c] = __ldg(bih + n) + __ldg(bhh + n);
    }
#pragma unroll
    for (int r = 0; r < 4; r++) {
        size_t m = (size_t)(m0 + tm * 4 + r);
        float4 o;
        upk2(acc[r][0], o.x, o.y);
        upk2(acc[r][1], o.z, o.w);
        o.x += bias[0]; o.y += bias[1]; o.z += bias[2]; o.w += bias[3];
        *(float4*)(d_G + m * G4H + n0 + tn * 4) = o;
    }
}

// ---------------- K2: fused persistent recurrent kernel (R6 base) ----------------
// GEMM CTAs (0..127): stage h, FFMA2 k-split GEMM, reduce+g_sm, flag-wait, cell -> d_mem.
// Attention CTAs (128..135): warp per batch; self-scored (registers), single-array
//   gather from d_mem, write d_mseq[i], publish flag. One gsync/step.
__global__ void __launch_bounds__(256, 1) lstm_persistent(const float* __restrict__ W_hh,
                                                          const float* __restrict__ w_t) {
    extern __shared__ __align__(16) float smem[];
    float* w2f  = smem;                     // [k][2*jp] pairs, stride W2S
    float* h2f  = smem + W2_ELE;            // [k][2*b] dup'd pairs, stride H2S
    float* p_sm = smem + W2_ELE + H2_ELE;   // partials [kg][b][j]
    float* g_sm = h2f;                      // gates [b][j] stride 68 (aliases h2; sync-ordered)

    int g = blockIdx.x, tx = threadIdx.x;
    int wrp = tx >> 5, lane = tx & 31;

    if (g < NGEMM) {
        int jg = g >> 2, bg = g & 3;
        int h0 = jg * 16;

        // ---- stage W pairs once ----
#pragma unroll
        for (int q2 = 0; q2 < 64; q2++) {
            int idx = q2 * 256 + tx;
            int jp = idx >> 9, k = idx & 511;
            int jj0 = 2 * jp, jj1 = 2 * jp + 1;
            int r0 = (jj0 >> 4) * H_ + h0 + (jj0 & 15);
            int r1 = (jj1 >> 4) * H_ + h0 + (jj1 & 15);
            float2 v;
            v.x = __ldg(W_hh + (size_t)r0 * H_ + k);
            v.y = __ldg(W_hh + (size_t)r1 * H_ + k);
            *(float2*)&w2f[k * W2S + 2 * jp] = v;
        }
        __syncthreads();

        int kg = wrp & 3, half = wrp >> 2;
        int bq = lane >> 3, jq = lane & 7;
        int b0 = half * 8 + bq * 2;

        int bl = tx >> 4;
        int j0 = (tx & 15) * 4;
        int hi = tx & 15;
        const float* gsrc = d_G + ((size_t)bg * 16 + bl) * G4H
                            + (size_t)(j0 >> 4) * H_ + h0 + (j0 & 15);
        float cstate = 0.f;

        for (int i = 0; i < T_; ++i) {
            // ---- prefetch input-proj gates for this thread's reduce slice ----
            float4 gpre = __ldcg((const float4*)(gsrc + (size_t)i * B_ * G4H));

            // ---- stage h2 dup'd from d_mem[i] ----
            const float* hrow = d_mem + (size_t)i * BH + (size_t)bg * 16 * H_;
#pragma unroll
            for (int q2 = 0; q2 < 8; q2++) {
                int it = q2 * 256 + tx;          // [0,2048) float4s
                int b = it & 15, kq = it >> 4;   // kq in [0,128)
                float4 v = __ldcg((const float4*)(hrow + (size_t)b * H_ + kq * 4));
                *(float2*)&h2f[(4*kq+0) * H2S + 2*b] = make_float2(v.x, v.x);
                *(float2*)&h2f[(4*kq+1) * H2S + 2*b] = make_float2(v.y, v.y);
                *(float2*)&h2f[(4*kq+2) * H2S + 2*b] = make_float2(v.z, v.z);
                *(float2*)&h2f[(4*kq+3) * H2S + 2*b] = make_float2(v.w, v.w);
            }
            __syncthreads();

            // ---- FFMA2 k-loop: 128 k per warp, 2b x 8j per lane ----
            {
                unsigned long long a0=0,a1=0,a2=0,a3=0,a4=0,a5=0,a6=0,a7=0;
                const float* wp = w2f + (size_t)(kg * 128) * W2S + 4 * jq;
                const float* hp = h2f + (size_t)(kg * 128) * H2S + 2 * b0;
#pragma unroll 8
                for (int k = 0; k < 128; k++) {
                    ulonglong2 hv = *(const ulonglong2*)hp;
                    ulonglong2 wA = *(const ulonglong2*)wp;
                    ulonglong2 wB = *(const ulonglong2*)(wp + 32);
                    a0 = fma2(hv.x, wA.x, a0); a1 = fma2(hv.x, wA.y, a1);
                    a2 = fma2(hv.x, wB.x, a2); a3 = fma2(hv.x, wB.y, a3);
                    a4 = fma2(hv.y, wA.x, a4); a5 = fma2(hv.y, wA.y, a5);
                    a6 = fma2(hv.y, wB.x, a6); a7 = fma2(hv.y, wB.y, a7);
                    wp += W2S; hp += H2S;
                }
                float* pb = p_sm + kg * 1024 + b0 * 64 + 4 * jq;
                float4 o;
                upk2(a0, o.x, o.y); upk2(a1, o.z, o.w); *(float4*)pb = o;
                upk2(a2, o.x, o.y); upk2(a3, o.z, o.w); *(float4*)(pb + 32) = o;
                upk2(a4, o.x, o.y); upk2(a5, o.z, o.w); *(float4*)(pb + 64) = o;
                upk2(a6, o.x, o.y); upk2(a7, o.z, o.w); *(float4*)(pb + 96) = o;
            }

            // ---- wait for attention m_t of this step ----
            if (tx == 0) {
                volatile unsigned* fl = (volatile unsigned*)d_aflag;
                while (fl[i] < (unsigned)NATT_CTA) { }
            }
            __syncthreads();   // partials complete + flag visible

            // ---- reduce 4 partials + input proj -> g_sm ----
            {
                float4 s = gpre;
#pragma unroll
                for (int kk = 0; kk < 4; kk++) {
                    float4 p = *(const float4*)&p_sm[kk * 1024 + bl * 64 + j0];
                    s.x += p.x; s.y += p.y; s.z += p.z; s.w += p.w;
                }
                *(float4*)&g_sm[bl * 68 + j0] = s;
            }
            __syncthreads();

            // ---- LSTM cell: (b = bg*16+bl, h = h0+hi) ----
            {
                float gi = g_sm[bl * 68 + hi];
                float gf = g_sm[bl * 68 + 16 + hi];
                float gg = g_sm[bl * 68 + 32 + hi];
                float go = g_sm[bl * 68 + 48 + hi];
                size_t off = (size_t)(bg * 16 + bl) * H_ + h0 + hi;
                float mt = __ldcg(d_mseq + (size_t)i * BH + off);

                float cn = sigf(gf) * cstate + sigf(gi) * tanhf(gg);
                float hn = sigf(go) * tanhf(cn);
                cstate = cn;
                d_mem[(size_t)(i + 1) * BH + off] = hn + mt;
            }

            gsync(i, NCTA);
        }
    } else {
        // ---------------- attention CTAs: warp per batch, self-scored ----------------
        int b = (g - NGEMM) * 8 + wrp;
        float4 wt2r[4];
#pragma unroll
        for (int q = 0; q < 4; q++)
            wt2r[q] = *(const float4*)(w_t + H_ + q * 128 + lane * 4);

        float v[8];                        // scores: v[r] = score(t = lane + 32r)
#pragma unroll
        for (int r = 0; r < 8; r++) v[r] = -INFINITY;

        const float* memb = d_mem + (size_t)b * H_;

        for (int i = 0; i < T_; ++i) {
            // ---- score of new row t=i from mem[i] (coalesced) ----
            float part = 0.f;
#pragma unroll
            for (int q = 0; q < 4; q++) {
                const float4 a = __ldcg((const float4*)(memb + (size_t)i * BH + q * 128 + lane * 4));
                part += tanhf(a.x) * wt2r[q].x;
                part += tanhf(a.y) * wt2r[q].y;
                part += tanhf(a.z) * wt2r[q].z;
                part += tanhf(a.w) * wt2r[q].w;
            }
#pragma unroll
            for (int o = 16; o > 0; o >>= 1) part += __shfl_xor_sync(0xffffffffu, part, o);
            {
                int rr = i >> 5, ll = i & 31;
#pragma unroll
                for (int r = 0; r < 8; r++)
                    if (r == rr && lane == ll) v[r] = part;
            }

            int n = i + 1;
            float mn = INFINITY;
#pragma unroll
            for (int r = 0; r < 8; r++) {
                int t = lane + 32 * r;
                if (t < n) mn = fminf(mn, v[r]);
            }
#pragma unroll
            for (int o = 16; o > 0; o >>= 1) mn = fminf(mn, __shfl_xor_sync(0xffffffffu, mn, o));

            float w[8];
#pragma unroll
            for (int r = 0; r < 8; r++) w[r] = v[r];
            float topv[5]; int topt[5];
#pragma unroll
            for (int k5 = 0; k5 < 5; k5++) {
                float bv = -INFINITY; int bt = 1 << 30;
#pragma unroll
                for (int r = 0; r < 8; r++) {
                    int t = lane + 32 * r;
                    if (w[r] > bv) { bv = w[r]; bt = t; }
                }
#pragma unroll
                for (int o = 16; o > 0; o >>= 1) {
                    float ov = __shfl_xor_sync(0xffffffffu, bv, o);
                    int   ot = __shfl_xor_sync(0xffffffffu, bt, o);
                    if (ov > bv || (ov == bv && ot < bt)) { bv = ov; bt = ot; }
                }
                topv[k5] = bv; topt[k5] = bt;
                int rr = bt >> 5;
                if ((bt & 31) == lane && rr >= 0 && rr < 8) w[rr] = -INFINITY;
            }
            float delta = ((n <= 5) ? mn : topv[4]) + 1e-7f;
            float wk[5]; float sum = 0.f;
#pragma unroll
            for (int k5 = 0; k5 < 5; k5++) { wk[k5] = fmaxf(topv[k5] - delta, 0.f); sum += wk[k5]; }
            float inv = 1.f / (sum + 1e-7f);

            // gather m_t = sum wk * mem[t'] — single array, coalesced float4
            float4 acc4[4];
#pragma unroll
            for (int q = 0; q < 4; q++) acc4[q] = make_float4(0.f, 0.f, 0.f, 0.f);
#pragma unroll
            for (int k5 = 0; k5 < 5; k5++) {
                float wv = wk[k5] * inv;
                if (wv > 0.f) {
                    const float* rowp = memb + (size_t)topt[k5] * BH;
#pragma unroll
                    for (int q = 0; q < 4; q++) {
                        const float4 a = __ldg((const float4*)(rowp + q * 128 + lane * 4));
                        acc4[q].x = fmaf(wv, a.x, acc4[q].x);
                        acc4[q].y = fmaf(wv, a.y, acc4[q].y);
                        acc4[q].z = fmaf(wv, a.z, acc4[q].z);
                        acc4[q].w = fmaf(wv, a.w, acc4[q].w);
                    }
                }
            }
            float* mw = d_mseq + (size_t)i * BH + (size_t)b * H_;
#pragma unroll
            for (int q = 0; q < 4; q++)
                *(float4*)(mw + q * 128 + lane * 4) = acc4[q];

            // publish: m_t for step i is ready
            __threadfence();
            __syncthreads();
            if (tx == 0) atomicAdd(&d_aflag[i], 1u);

            gsync(i, NCTA);
        }
    }
}

// ---------------- K3: out = [h_seq | m_seq] @ fc_w^T + fc_b (R6 version) ----------------
__global__ void __launch_bounds__(256) fc_final_kernel(const float* __restrict__ fcw,
                                                       const float* __restrict__ fcb,
                                                       float* __restrict__ out) {
    __shared__ __align__(16) float a_s[16][64];
    __shared__ __align__(16) float b_s[16][64];
    int tx = threadIdx.x;
    int m0 = blockIdx.x * 64;
    int tm = tx & 15, tn = tx >> 4;
    float acc[4][4];
#pragma unroll
    for (int r = 0; r < 4; r++)
#pragma unroll
        for (int c = 0; c < 4; c++) acc[r][c] = 0.f;

    int row = tx >> 2, qd = tx & 3;
    int m = m0 + row, t = m >> 6, b = m & 63;
    for (int k0 = 0; k0 < 2 * H_; k0 += 16) {
        int k = k0 + qd * 4;
        const float* src = (k < H_)
            ? (d_mem + ((size_t)(t + 1) * B_ + b) * H_ + k)          // h_seq[t] = mem[t+1]
            : (d_mseq + ((size_t)t * B_ + b) * H_ + (k - H_));        // m_seq[t]
        float4 av = *(const float4*)src;
        float4 bv = *(const float4*)(fcw + (size_t)row * (2 * H_) + k);
        a_s[qd*4+0][row] = av.x; a_s[qd*4+1][row] = av.y; a_s[qd*4+2][row] = av.z; a_s[qd*4+3][row] = av.w;
        b_s[qd*4+0][row] = bv.x; b_s[qd*4+1][row] = bv.y; b_s[qd*4+2][row] = bv.z; b_s[qd*4+3][row] = bv.w;
        __syncthreads();
#pragma unroll
        for (int k2 = 0; k2 < 16; k2++) {
            float4 a = *(const float4*)&a_s[k2][tm * 4];
            float4 bb = *(const float4*)&b_s[k2][tn * 4];
            acc[0][0] = fmaf(a.x, bb.x, acc[0][0]); acc[0][1] = fmaf(a.x, bb.y, acc[0][1]);
            acc[0][2] = fmaf(a.x, bb.z, acc[0][2]); acc[0][3] = fmaf(a.x, bb.w, acc[0][3]);
            acc[1][0] = fmaf(a.y, bb.x, acc[1][0]); acc[1][1] = fmaf(a.y, bb.y, acc[1][1]);
            acc[1][2] = fmaf(a.y, bb.z, acc[1][2]); acc[1][3] = fmaf(a.y, bb.w, acc[1][3]);
            acc[2][0] = fmaf(a.z, bb.x, acc[2][0]); acc[2][1] = fmaf(a.z, bb.y, acc[2][1]);
            acc[2][2] = fmaf(a.z, bb.z, acc[2][2]); acc[2][3] = fmaf(a.z, bb.w, acc[2][3]);
            acc[3][0] = fmaf(a.w, bb.x, acc[3][0]); acc[3][1] = fmaf(a.w, bb.y, acc[3][1]);
            acc[3][2] = fmaf(a.w, bb.z, acc[3][2]); acc[3][3] = fmaf(a.w, bb.w, acc[3][3]);
        }
        __syncthreads();
    }
    float bias[4];
#pragma unroll
    for (int c = 0; c < 4; c++) bias[c] = __ldg(fcb + tn * 4 + c);
#pragma unroll
    for (int r = 0; r < 4; r++) {
        size_t mm = (size_t)(m0 + tm * 4 + r);
        float4 o;
        o.x = acc[r][0] + bias[0]; o.y = acc[r][1] + bias[1];
        o.z = acc[r][2] + bias[2]; o.w = acc[r][3] + bias[3];
        *(float4*)(out + mm * C_ + tn * 4) = o;
    }
}

// ---------------- launch ----------------
extern "C" void kernel_launch(void* const* d_in, const int* in_sizes, int n_in,
                              void* d_out, int out_size) {
    const float* x    = (const float*)d_in[0];
    const float* W_ih = (const float*)d_in[1];
    const float* W_hh = (const float*)d_in[2];
    const float* b_ih = (const float*)d_in[3];
    const float* b_hh = (const float*)d_in[4];
    const float* w_t  = (const float*)d_in[5];
    const float* fc_w = (const float*)d_in[6];
    const float* fc_b = (const float*)d_in[7];
    float* out = (float*)d_out;

    static int smem_set = 0;
    if (!smem_set) {
        cudaFuncSetAttribute(lstm_persistent,
                             cudaFuncAttributeMaxDynamicSharedMemorySize, SMEM_BYTES);
        smem_set = 1;
    }

    // ncu profiles launch #4 -> keep lstm_persistent there.
    reset_kernel<<<64, 512>>>();
    gemm_ih_kernel<<<dim3(G4H / 64, (T_ * B_) / 64), 256>>>(x, W_ih, b_ih, b_hh);
    noop_kernel<<<1, 1>>>();
    lstm_persistent<<<NCTA, 256, SMEM_BYTES>>>(W_hh, w_t);
    fc_final_kernel<<<(T_ * B_) / 64, 256>>>(fc_w, fc_b, out);
}

// round 12
// speedup vs baseline: 1.6439x; 1.1898x over previous
#include <cuda_runtime.h>
#include <math.h>
#include <stdint.h>

#define T_   256
#define B_   64
#define I_   256
#define H_   512
#define C_   64
#define G4H  2048
#define BH   (B_*H_)      // 32768
#define NCTA 136
#define NGEMM 128
#define NATT_CTA 8
#define NSYNC 256

// lstm smem (floats): w2 [k][jp-pairs] stride 68, h2dup [k][b-dup] stride 36,
// partials [kg][b][j] 4*1024. g_sm (16x68) aliases h2 start.
#define W2S 68
#define H2S 36
#define W2_ELE (512 * W2S)        // 34816
#define H2_ELE (512 * H2S)        // 18432
#define PT_ELE (4 * 1024)         // 4096
#define SMEM_FLOATS (W2_ELE + H2_ELE + PT_ELE)
#define SMEM_BYTES  (SMEM_FLOATS * 4)   // 229376 B

// ---------------- static device scratch ----------------
__device__ float    d_G[(size_t)T_ * B_ * G4H];
__device__ float    d_mem[(size_t)(T_ + 1) * BH];   // mem rows; mem[i+1] = h_out[i]
__device__ float    d_mseq[(size_t)T_ * BH];        // m_t per step
__device__ float    d_s2[B_ * (T_ + 1)];            // cached memory scores, [b][t]
__device__ unsigned d_bar[NSYNC];
__device__ unsigned d_aflag[NSYNC];

__device__ __forceinline__ float sigf(float x) { return 1.f / (1.f + __expf(-x)); }

__device__ __forceinline__ void upk2(unsigned long long v, float& x, float& y) {
    asm("mov.b64 {%0, %1}, %2;" : "=f"(x), "=f"(y) : "l"(v));
}
__device__ __forceinline__ unsigned long long fma2(unsigned long long a,
                                                   unsigned long long b,
                                                   unsigned long long c) {
    unsigned long long d;
    asm("fma.rn.f32x2 %0, %1, %2, %3;" : "=l"(d) : "l"(a), "l"(b), "l"(c));
    return d;
}

// release/acquire grid barrier; fence+arrive+spin by thread 0 only
__device__ __forceinline__ void gsync(int slot, unsigned nct) {
    __syncthreads();
    if (threadIdx.x == 0) {
        __threadfence();
        atomicAdd(&d_bar[slot], 1u);
        while (*((volatile unsigned*)&d_bar[slot]) < nct) { }
        __threadfence();
    }
    __syncthreads();
}

__global__ void noop_kernel() {}

// ---------------- reset (R6) ----------------
__global__ void reset_kernel() {
    int id = blockIdx.x * blockDim.x + threadIdx.x;   // 32768 threads
    d_mem[id] = 0.f;
    if (id < B_ * (T_ + 1)) d_s2[id] = 0.f;
    if (id < NSYNC) { d_bar[id] = 0u; d_aflag[id] = 0u; }
}

// ---------------- K1: G = x @ W_ih^T + (b_ih + b_hh) (R6 scalar) ----------------
__global__ void __launch_bounds__(256) gemm_ih_kernel(const float* __restrict__ X,
                                                      const float* __restrict__ Wih,
                                                      const float* __restrict__ bih,
                                                      const float* __restrict__ bhh) {
    __shared__ __align__(16) float a_s[16][64];
    __shared__ __align__(16) float b_s[16][64];
    int tx = threadIdx.x;
    int m0 = blockIdx.y * 64, n0 = blockIdx.x * 64;
    int tm = tx & 15, tn = tx >> 4;
    float acc[4][4];
#pragma unroll
    for (int r = 0; r < 4; r++)
#pragma unroll
        for (int c = 0; c < 4; c++) acc[r][c] = 0.f;

    int row = tx >> 2, qd = tx & 3;
    for (int k0 = 0; k0 < I_; k0 += 16) {
        float4 av = *(const float4*)(X + (size_t)(m0 + row) * I_ + k0 + qd * 4);
        float4 bv = *(const float4*)(Wih + (size_t)(n0 + row) * I_ + k0 + qd * 4);
        a_s[qd*4+0][row] = av.x; a_s[qd*4+1][row] = av.y; a_s[qd*4+2][row] = av.z; a_s[qd*4+3][row] = av.w;
        b_s[qd*4+0][row] = bv.x; b_s[qd*4+1][row] = bv.y; b_s[qd*4+2][row] = bv.z; b_s[qd*4+3][row] = bv.w;
        __syncthreads();
#pragma unroll
        for (int k = 0; k < 16; k++) {
            float4 a = *(const float4*)&a_s[k][tm * 4];
            float4 b = *(const float4*)&b_s[k][tn * 4];
            acc[0][0] = fmaf(a.x, b.x, acc[0][0]); acc[0][1] = fmaf(a.x, b.y, acc[0][1]);
            acc[0][2] = fmaf(a.x, b.z, acc[0][2]); acc[0][3] = fmaf(a.x, b.w, acc[0][3]);
            acc[1][0] = fmaf(a.y, b.x, acc[1][0]); acc[1][1] = fmaf(a.y, b.y, acc[1][1]);
            acc[1][2] = fmaf(a.y, b.z, acc[1][2]); acc[1][3] = fmaf(a.y, b.w, acc[1][3]);
            acc[2][0] = fmaf(a.z, b.x, acc[2][0]); acc[2][1] = fmaf(a.z, b.y, acc[2][1]);
            acc[2][2] = fmaf(a.z, b.z, acc[2][2]); acc[2][3] = fmaf(a.z, b.w, acc[2][3]);
            acc[3][0] = fmaf(a.w, b.x, acc[3][0]); acc[3][1] = fmaf(a.w, b.y, acc[3][1]);
            acc[3][2] = fmaf(a.w, b.z, acc[3][2]); acc[3][3] = fmaf(a.w, b.w, acc[3][3]);
        }
        __syncthreads();
    }
    float bias[4];
#pragma unroll
    for (int c = 0; c < 4; c++) {
        int n = n0 + tn * 4 + c;
        bias[c] = __ldg(bih + n) + __ldg(bhh + n);
    }
#pragma unroll
    for (int r = 0; r < 4; r++) {
        size_t m = (size_t)(m0 + tm * 4 + r);
        float4 o;
        o.x = acc[r][0] + bias[0]; o.y = acc[r][1] + bias[1];
        o.z = acc[r][2] + bias[2]; o.w = acc[r][3] + bias[3];
        *(float4*)(d_G + m * G4H + n0 + tn * 4) = o;
    }
}

// ---------------- K2: fused persistent recurrent kernel (R6, byte-identical) ----------------
__global__ void __launch_bounds__(256, 1) lstm_persistent(const float* __restrict__ W_hh,
                                                          const float* __restrict__ w_t) {
    extern __shared__ __align__(16) float smem[];
    float* w2f  = smem;                     // [k][2*jp] pairs, stride W2S
    float* h2f  = smem + W2_ELE;            // [k][2*b] dup'd pairs, stride H2S
    float* p_sm = smem + W2_ELE + H2_ELE;   // partials [kg][b][j]
    float* g_sm = h2f;                      // gates [b][j] stride 68 (aliases h2; sync-ordered)

    int g = blockIdx.x, tx = threadIdx.x;
    int wrp = tx >> 5, lane = tx & 31;

    if (g < NGEMM) {
        int jg = g >> 2, bg = g & 3;
        int h0 = jg * 16;

        // ---- stage W pairs once ----
#pragma unroll
        for (int q2 = 0; q2 < 64; q2++) {
            int idx = q2 * 256 + tx;
            int jp = idx >> 9, k = idx & 511;
            int jj0 = 2 * jp, jj1 = 2 * jp + 1;
            int r0 = (jj0 >> 4) * H_ + h0 + (jj0 & 15);
            int r1 = (jj1 >> 4) * H_ + h0 + (jj1 & 15);
            float2 v;
            v.x = __ldg(W_hh + (size_t)r0 * H_ + k);
            v.y = __ldg(W_hh + (size_t)r1 * H_ + k);
            *(float2*)&w2f[k * W2S + 2 * jp] = v;
        }
        __syncthreads();

        int kg = wrp & 3, half = wrp >> 2;
        int bq = lane >> 3, jq = lane & 7;
        int b0 = half * 8 + bq * 2;

        int bl = tx >> 4;
        int j0 = (tx & 15) * 4;
        int hi = tx & 15;
        const float* gsrc = d_G + ((size_t)bg * 16 + bl) * G4H
                            + (size_t)(j0 >> 4) * H_ + h0 + (j0 & 15);
        float wt2v = __ldg(w_t + H_ + h0 + hi);
        float cstate = 0.f;

        for (int i = 0; i < T_; ++i) {
            float4 gpre = __ldcg((const float4*)(gsrc + (size_t)i * B_ * G4H));

            // ---- stage h2 dup'd from d_mem[i] ----
            const float* hrow = d_mem + (size_t)i * BH + (size_t)bg * 16 * H_;
#pragma unroll
            for (int q2 = 0; q2 < 8; q2++) {
                int it = q2 * 256 + tx;
                int b = it & 15, kq = it >> 4;
                float4 v = __ldcg((const float4*)(hrow + (size_t)b * H_ + kq * 4));
                *(float2*)&h2f[(4*kq+0) * H2S + 2*b] = make_float2(v.x, v.x);
                *(float2*)&h2f[(4*kq+1) * H2S + 2*b] = make_float2(v.y, v.y);
                *(float2*)&h2f[(4*kq+2) * H2S + 2*b] = make_float2(v.z, v.z);
                *(float2*)&h2f[(4*kq+3) * H2S + 2*b] = make_float2(v.w, v.w);
            }
            __syncthreads();

            // ---- FFMA2 k-loop: 128 k per warp, 2b x 8j per lane ----
            {
                unsigned long long a0=0,a1=0,a2=0,a3=0,a4=0,a5=0,a6=0,a7=0;
                const float* wp = w2f + (size_t)(kg * 128) * W2S + 4 * jq;
                const float* hp = h2f + (size_t)(kg * 128) * H2S + 2 * b0;
#pragma unroll 8
                for (int k = 0; k < 128; k++) {
                    ulonglong2 hv = *(const ulonglong2*)hp;
                    ulonglong2 wA = *(const ulonglong2*)wp;
                    ulonglong2 wB = *(const ulonglong2*)(wp + 32);
                    a0 = fma2(hv.x, wA.x, a0); a1 = fma2(hv.x, wA.y, a1);
                    a2 = fma2(hv.x, wB.x, a2); a3 = fma2(hv.x, wB.y, a3);
                    a4 = fma2(hv.y, wA.x, a4); a5 = fma2(hv.y, wA.y, a5);
                    a6 = fma2(hv.y, wB.x, a6); a7 = fma2(hv.y, wB.y, a7);
                    wp += W2S; hp += H2S;
                }
                float* pb = p_sm + kg * 1024 + b0 * 64 + 4 * jq;
                float4 o;
                upk2(a0, o.x, o.y); upk2(a1, o.z, o.w); *(float4*)pb = o;
                upk2(a2, o.x, o.y); upk2(a3, o.z, o.w); *(float4*)(pb + 32) = o;
                upk2(a4, o.x, o.y); upk2(a5, o.z, o.w); *(float4*)(pb + 64) = o;
                upk2(a6, o.x, o.y); upk2(a7, o.z, o.w); *(float4*)(pb + 96) = o;
            }

            // ---- wait for attention m_t of this step ----
            if (tx == 0) {
                volatile unsigned* fl = (volatile unsigned*)d_aflag;
                while (fl[i] < (unsigned)NATT_CTA) { }
            }
            __syncthreads();   // partials complete + flag visible

            // ---- reduce 4 partials + input proj -> g_sm ----
            {
                float4 s = gpre;
#pragma unroll
                for (int kk = 0; kk < 4; kk++) {
                    float4 p = *(const float4*)&p_sm[kk * 1024 + bl * 64 + j0];
                    s.x += p.x; s.y += p.y; s.z += p.z; s.w += p.w;
                }
                *(float4*)&g_sm[bl * 68 + j0] = s;
            }
            __syncthreads();

            // ---- LSTM cell: (b = bg*16+bl, h = h0+hi) ----
            {
                float gi = g_sm[bl * 68 + hi];
                float gf = g_sm[bl * 68 + 16 + hi];
                float gg = g_sm[bl * 68 + 32 + hi];
                float go = g_sm[bl * 68 + 48 + hi];
                size_t off = (size_t)(bg * 16 + bl) * H_ + h0 + hi;
                float mt = __ldcg(d_mseq + (size_t)i * BH + off);

                float cn = sigf(gf) * cstate + sigf(gi) * tanhf(gg);
                float hn = sigf(go) * tanhf(cn);
                cstate = cn;
                float ho = hn + mt;
                d_mem[(size_t)(i + 1) * BH + off] = ho;

                float part = tanhf(ho) * wt2v;
#pragma unroll
                for (int o = 8; o > 0; o >>= 1) part += __shfl_xor_sync(0xffffffffu, part, o);
                if ((lane & 15) == 0)
                    atomicAdd(&d_s2[(bg * 16 + bl) * (T_ + 1) + (i + 1)], part);
            }

            gsync(i, NCTA);
        }
    } else {
        // ---------------- attention CTAs: warp per batch (R6) ----------------
        int b = (g - NGEMM) * 8 + wrp;
        for (int i = 0; i < T_; ++i) {
            int n = i + 1;
            float v[8];
            float mn = INFINITY;
#pragma unroll
            for (int r = 0; r < 8; r++) {
                int t = lane + 32 * r;
                if (t < n) {
                    float s = __ldcg(d_s2 + b * (T_ + 1) + t);
                    v[r] = s;
                    mn = fminf(mn, s);
                } else {
                    v[r] = -INFINITY;
                }
            }
#pragma unroll
            for (int o = 16; o > 0; o >>= 1) mn = fminf(mn, __shfl_xor_sync(0xffffffffu, mn, o));
            float topv[5]; int topt[5];
#pragma unroll
            for (int k5 = 0; k5 < 5; k5++) {
                float bv = -INFINITY; int bt = 1 << 30;
#pragma unroll
                for (int r = 0; r < 8; r++) {
                    int t = lane + 32 * r;
                    if (v[r] > bv) { bv = v[r]; bt = t; }
                }
#pragma unroll
                for (int o = 16; o > 0; o >>= 1) {
                    float ov = __shfl_xor_sync(0xffffffffu, bv, o);
                    int   ot = __shfl_xor_sync(0xffffffffu, bt, o);
                    if (ov > bv || (ov == bv && ot < bt)) { bv = ov; bt = ot; }
                }
                topv[k5] = bv; topt[k5] = bt;
                int rr = bt >> 5;
                if ((bt & 31) == lane && rr >= 0 && rr < 8) v[rr] = -INFINITY;
            }
            float delta = ((n <= 5) ? mn : topv[4]) + 1e-7f;
            float wk[5]; float sum = 0.f;
#pragma unroll
            for (int k5 = 0; k5 < 5; k5++) { wk[k5] = fmaxf(topv[k5] - delta, 0.f); sum += wk[k5]; }
            float inv = 1.f / (sum + 1e-7f);
            float acc[16];
#pragma unroll
            for (int r = 0; r < 16; r++) acc[r] = 0.f;
#pragma unroll
            for (int k5 = 0; k5 < 5; k5++) {
                float wv = wk[k5] * inv;
                if (wv > 0.f) {
                    const float* rowp = d_mem + (size_t)topt[k5] * BH + (size_t)b * H_;
#pragma unroll
                    for (int r = 0; r < 16; r++) acc[r] = fmaf(wv, __ldg(rowp + lane + 32 * r), acc[r]);
                }
            }
            float* mrow = d_mseq + (size_t)i * BH + (size_t)b * H_;
#pragma unroll
            for (int r = 0; r < 16; r++) mrow[lane + 32 * r] = acc[r];

            __threadfence();
            __syncthreads();
            if (tx == 0) atomicAdd(&d_aflag[i], 1u);

            gsync(i, NCTA);
        }
    }
}

// ---------------- K3: out = [h_seq | m_seq] @ fc_w^T + fc_b ----------------
// NEW: 32x64 tiles, 512 CTAs (2x wave balance), warp-coalesced output.
// Compute map: tm = tx>>5 (8 m-threads, 4 rows each), tn = tx&31 (32 n-threads, 2 cols each).
__global__ void __launch_bounds__(256) fc_final_kernel(const float* __restrict__ fcw,
                                                       const float* __restrict__ fcb,
                                                       float* __restrict__ out) {
    __shared__ __align__(16) float a_s[16][36];   // [k][m] pad to 36
    __shared__ __align__(16) float b_s[16][64];   // [k][n]
    int tx = threadIdx.x;
    int m0 = blockIdx.x * 32;
    int tm = tx >> 5, tn = tx & 31;
    float acc[4][2];
#pragma unroll
    for (int r = 0; r < 4; r++) { acc[r][0] = 0.f; acc[r][1] = 0.f; }

    int arow = tx >> 2, aqd = tx & 3;     // a loader (tx<128): 32 rows x 4 k-quads
    int am = m0 + (arow & 31), at = am >> 6, ab = am & 63;
    int brow = tx >> 2, bqd = tx & 3;     // b loader: 64 rows x 4 k-quads

    for (int k0 = 0; k0 < 2 * H_; k0 += 16) {
        if (tx < 128) {
            int k = k0 + aqd * 4;
            const float* src = (k < H_)
                ? (d_mem + ((size_t)(at + 1) * B_ + ab) * H_ + k)        // h_seq[t]=mem[t+1]
                : (d_mseq + ((size_t)at * B_ + ab) * H_ + (k - H_));      // m_seq[t]
            float4 av = *(const float4*)src;
            a_s[aqd*4+0][arow] = av.x; a_s[aqd*4+1][arow] = av.y;
            a_s[aqd*4+2][arow] = av.z; a_s[aqd*4+3][arow] = av.w;
        }
        {
            float4 bv = *(const float4*)(fcw + (size_t)brow * (2 * H_) + k0 + bqd * 4);
            b_s[bqd*4+0][brow] = bv.x; b_s[bqd*4+1][brow] = bv.y;
            b_s[bqd*4+2][brow] = bv.z; b_s[bqd*4+3][brow] = bv.w;
        }
        __syncthreads();
#pragma unroll
        for (int k = 0; k < 16; k++) {
            float4 a = *(const float4*)&a_s[k][tm * 4];     // warp-broadcast
            float2 bb = *(const float2*)&b_s[k][tn * 2];    // 2 wavefronts
            acc[0][0] = fmaf(a.x, bb.x, acc[0][0]); acc[0][1] = fmaf(a.x, bb.y, acc[0][1]);
            acc[1][0] = fmaf(a.y, bb.x, acc[1][0]); acc[1][1] = fmaf(a.y, bb.y, acc[1][1]);
            acc[2][0] = fmaf(a.z, bb.x, acc[2][0]); acc[2][1] = fmaf(a.z, bb.y, acc[2][1]);
            acc[3][0] = fmaf(a.w, bb.x, acc[3][0]); acc[3][1] = fmaf(a.w, bb.y, acc[3][1]);
        }
        __syncthreads();
    }
    float b0f = __ldg(fcb + tn * 2), b1f = __ldg(fcb + tn * 2 + 1);
#pragma unroll
    for (int r = 0; r < 4; r++) {
        size_t mm = (size_t)(m0 + tm * 4 + r);
        float2 o = make_float2(acc[r][0] + b0f, acc[r][1] + b1f);
        *(float2*)(out + mm * C_ + tn * 2) = o;   // warp: 64 consecutive floats
    }
}

// ---------------- launch ----------------
extern "C" void kernel_launch(void* const* d_in, const int* in_sizes, int n_in,
                              void* d_out, int out_size) {
    const float* x    = (const float*)d_in[0];
    const float* W_ih = (const float*)d_in[1];
    const float* W_hh = (const float*)d_in[2];
    const float* b_ih = (const float*)d_in[3];
    const float* b_hh = (const float*)d_in[4];
    const float* w_t  = (const float*)d_in[5];
    const float* fc_w = (const float*)d_in[6];
    const float* fc_b = (const float*)d_in[7];
    float* out = (float*)d_out;

    static int smem_set = 0;
    if (!smem_set) {
        cudaFuncSetAttribute(lstm_persistent,
                             cudaFuncAttributeMaxDynamicSharedMemorySize, SMEM_BYTES);
        smem_set = 1;
    }

    // ncu profiles launch #4 -> place gemm_ih there this round (K1 profile intel).
    reset_kernel<<<64, 512>>>();
    noop_kernel<<<1, 1>>>();
    noop_kernel<<<1, 1>>>();
    gemm_ih_kernel<<<dim3(G4H / 64, (T_ * B_) / 64), 256>>>(x, W_ih, b_ih, b_hh);
    lstm_persistent<<<NCTA, 256, SMEM_BYTES>>>(W_hh, w_t);
    fc_final_kernel<<<(T_ * B_) / 32, 256>>>(fc_w, fc_b, out);
}

// round 14
// speedup vs baseline: 1.6830x; 1.0238x over previous
#include <cuda_runtime.h>
#include <math.h>
#include <stdint.h>

#define T_   256
#define B_   64
#define I_   256
#define H_   512
#define C_   64
#define G4H  2048
#define BH   (B_*H_)      // 32768
#define NCTA 136
#define NGEMM 128
#define NATT_CTA 8
#define NSYNC 256

// lstm smem (floats): w2 [k][jp-pairs] stride 68, h2dup [k][b-dup] stride 36,
// partials [kg][b][j] 4*1024. g_sm (16x68) aliases h2 start.
#define W2S 68
#define H2S 36
#define W2_ELE (512 * W2S)        // 34816
#define H2_ELE (512 * H2S)        // 18432
#define PT_ELE (4 * 1024)         // 4096
#define SMEM_FLOATS (W2_ELE + H2_ELE + PT_ELE)
#define SMEM_BYTES  (SMEM_FLOATS * 4)   // 229376 B

// ---------------- static device scratch ----------------
__device__ float    d_G[(size_t)T_ * B_ * G4H];
__device__ float    d_mem[(size_t)(T_ + 1) * BH];   // mem rows; mem[i+1] = h_out[i]
__device__ float    d_mseq[(size_t)T_ * BH];        // m_t per step
__device__ float    d_s2[B_ * (T_ + 1)];            // cached memory scores, [b][t]
__device__ unsigned d_bar[NSYNC];
__device__ unsigned d_aflag[NSYNC];

__device__ __forceinline__ float sigf(float x) { return 1.f / (1.f + __expf(-x)); }

__device__ __forceinline__ void upk2(unsigned long long v, float& x, float& y) {
    asm("mov.b64 {%0, %1}, %2;" : "=f"(x), "=f"(y) : "l"(v));
}
__device__ __forceinline__ unsigned long long fma2(unsigned long long a,
                                                   unsigned long long b,
                                                   unsigned long long c) {
    unsigned long long d;
    asm("fma.rn.f32x2 %0, %1, %2, %3;" : "=l"(d) : "l"(a), "l"(b), "l"(c));
    return d;
}

// release/acquire grid barrier; fence+arrive+spin by thread 0 only
__device__ __forceinline__ void gsync(int slot, unsigned nct) {
    __syncthreads();
    if (threadIdx.x == 0) {
        __threadfence();
        atomicAdd(&d_bar[slot], 1u);
        while (*((volatile unsigned*)&d_bar[slot]) < nct) { }
        __threadfence();
    }
    __syncthreads();
}

__global__ void noop_kernel() {}

// ---------------- reset (R6) ----------------
__global__ void reset_kernel() {
    int id = blockIdx.x * blockDim.x + threadIdx.x;   // 32768 threads
    d_mem[id] = 0.f;
    if (id < B_ * (T_ + 1)) d_s2[id] = 0.f;
    if (id < NSYNC) { d_bar[id] = 0u; d_aflag[id] = 0u; }
}

// ---------------- K1 v2: G = x @ W_ih^T + (b_ih + b_hh) ----------------
// 128x128 tile, 256 threads, 8x8 micro-tile -> FMA:LDS ratio 64:6 (FFMA-bound).
#define K1_AS 132
__global__ void __launch_bounds__(256) gemm_ih_kernel(const float* __restrict__ X,
                                                      const float* __restrict__ Wih,
                                                      const float* __restrict__ bih,
                                                      const float* __restrict__ bhh) {
    __shared__ __align__(16) float a_s[8][K1_AS];   // [k][m], 128 + pad
    __shared__ __align__(16) float b_s[8][K1_AS];   // [k][n]
    int tx = threadIdx.x;
    int m0 = blockIdx.y * 128, n0 = blockIdx.x * 128;
    int tm = tx & 15, tn = tx >> 4;                  // 16 x 16 thread grid
    int lrow = tx >> 1, lkq = tx & 1;                // loader: 128 rows x 2 k-quads

    float acc[8][8];
#pragma unroll
    for (int r = 0; r < 8; r++)
#pragma unroll
        for (int c = 0; c < 8; c++) acc[r][c] = 0.f;

    for (int k0 = 0; k0 < I_; k0 += 8) {
        // stage a: X[m0+lrow][k0+lkq*4 ..+3] -> a_s[k][m]
        float4 av = *(const float4*)(X + (size_t)(m0 + lrow) * I_ + k0 + lkq * 4);
        a_s[lkq*4+0][lrow] = av.x; a_s[lkq*4+1][lrow] = av.y;
        a_s[lkq*4+2][lrow] = av.z; a_s[lkq*4+3][lrow] = av.w;
        // stage b: Wih[n0+lrow][k0+lkq*4 ..+3] -> b_s[k][n]
        float4 bv = *(const float4*)(Wih + (size_t)(n0 + lrow) * I_ + k0 + lkq * 4);
        b_s[lkq*4+0][lrow] = bv.x; b_s[lkq*4+1][lrow] = bv.y;
        b_s[lkq*4+2][lrow] = bv.z; b_s[lkq*4+3][lrow] = bv.w;
        __syncthreads();
#pragma unroll
        for (int k = 0; k < 8; k++) {
            float4 aA = *(const float4*)&a_s[k][tm * 8];
            float4 aB = *(const float4*)&a_s[k][tm * 8 + 4];
            float4 bA = *(const float4*)&b_s[k][tn * 8];
            float4 bB = *(const float4*)&b_s[k][tn * 8 + 4];
            float am[8] = {aA.x, aA.y, aA.z, aA.w, aB.x, aB.y, aB.z, aB.w};
            float bn[8] = {bA.x, bA.y, bA.z, bA.w, bB.x, bB.y, bB.z, bB.w};
#pragma unroll
            for (int r = 0; r < 8; r++)
#pragma unroll
                for (int c = 0; c < 8; c++)
                    acc[r][c] = fmaf(am[r], bn[c], acc[r][c]);
        }
        __syncthreads();
    }
    float bias[8];
#pragma unroll
    for (int c = 0; c < 8; c++) {
        int n = n0 + tn * 8 + c;
        bias[c] = __ldg(bih + n) + __ldg(bhh + n);
    }
#pragma unroll
    for (int r = 0; r < 8; r++) {
        size_t m = (size_t)(m0 + tm * 8 + r);
        float* dst = d_G + m * G4H + n0 + tn * 8;
        float4 o0, o1;
        o0.x = acc[r][0] + bias[0]; o0.y = acc[r][1] + bias[1];
        o0.z = acc[r][2] + bias[2]; o0.w = acc[r][3] + bias[3];
        o1.x = acc[r][4] + bias[4]; o1.y = acc[r][5] + bias[5];
        o1.z = acc[r][6] + bias[6]; o1.w = acc[r][7] + bias[7];
        *(float4*)dst = o0;
        *(float4*)(dst + 4) = o1;
    }
}

// ---------------- K2: fused persistent recurrent kernel (R6, byte-identical) ----------------
__global__ void __launch_bounds__(256, 1) lstm_persistent(const float* __restrict__ W_hh,
                                                          const float* __restrict__ w_t) {
    extern __shared__ __align__(16) float smem[];
    float* w2f  = smem;                     // [k][2*jp] pairs, stride W2S
    float* h2f  = smem + W2_ELE;            // [k][2*b] dup'd pairs, stride H2S
    float* p_sm = smem + W2_ELE + H2_ELE;   // partials [kg][b][j]
    float* g_sm = h2f;                      // gates [b][j] stride 68 (aliases h2; sync-ordered)

    int g = blockIdx.x, tx = threadIdx.x;
    int wrp = tx >> 5, lane = tx & 31;

    if (g < NGEMM) {
        int jg = g >> 2, bg = g & 3;
        int h0 = jg * 16;

        // ---- stage W pairs once ----
#pragma unroll
        for (int q2 = 0; q2 < 64; q2++) {
            int idx = q2 * 256 + tx;
            int jp = idx >> 9, k = idx & 511;
            int jj0 = 2 * jp, jj1 = 2 * jp + 1;
            int r0 = (jj0 >> 4) * H_ + h0 + (jj0 & 15);
            int r1 = (jj1 >> 4) * H_ + h0 + (jj1 & 15);
            float2 v;
            v.x = __ldg(W_hh + (size_t)r0 * H_ + k);
            v.y = __ldg(W_hh + (size_t)r1 * H_ + k);
            *(float2*)&w2f[k * W2S + 2 * jp] = v;
        }
        __syncthreads();

        int kg = wrp & 3, half = wrp >> 2;
        int bq = lane >> 3, jq = lane & 7;
        int b0 = half * 8 + bq * 2;

        int bl = tx >> 4;
        int j0 = (tx & 15) * 4;
        int hi = tx & 15;
        const float* gsrc = d_G + ((size_t)bg * 16 + bl) * G4H
                            + (size_t)(j0 >> 4) * H_ + h0 + (j0 & 15);
        float wt2v = __ldg(w_t + H_ + h0 + hi);
        float cstate = 0.f;

        for (int i = 0; i < T_; ++i) {
            float4 gpre = __ldcg((const float4*)(gsrc + (size_t)i * B_ * G4H));

            // ---- stage h2 dup'd from d_mem[i] ----
            const float* hrow = d_mem + (size_t)i * BH + (size_t)bg * 16 * H_;
#pragma unroll
            for (int q2 = 0; q2 < 8; q2++) {
                int it = q2 * 256 + tx;
                int b = it & 15, kq = it >> 4;
                float4 v = __ldcg((const float4*)(hrow + (size_t)b * H_ + kq * 4));
                *(float2*)&h2f[(4*kq+0) * H2S + 2*b] = make_float2(v.x, v.x);
                *(float2*)&h2f[(4*kq+1) * H2S + 2*b] = make_float2(v.y, v.y);
                *(float2*)&h2f[(4*kq+2) * H2S + 2*b] = make_float2(v.z, v.z);
                *(float2*)&h2f[(4*kq+3) * H2S + 2*b] = make_float2(v.w, v.w);
            }
            __syncthreads();

            // ---- FFMA2 k-loop: 128 k per warp, 2b x 8j per lane ----
            {
                unsigned long long a0=0,a1=0,a2=0,a3=0,a4=0,a5=0,a6=0,a7=0;
                const float* wp = w2f + (size_t)(kg * 128) * W2S + 4 * jq;
                const float* hp = h2f + (size_t)(kg * 128) * H2S + 2 * b0;
#pragma unroll 8
                for (int k = 0; k < 128; k++) {
                    ulonglong2 hv = *(const ulonglong2*)hp;
                    ulonglong2 wA = *(const ulonglong2*)wp;
                    ulonglong2 wB = *(const ulonglong2*)(wp + 32);
                    a0 = fma2(hv.x, wA.x, a0); a1 = fma2(hv.x, wA.y, a1);
                    a2 = fma2(hv.x, wB.x, a2); a3 = fma2(hv.x, wB.y, a3);
                    a4 = fma2(hv.y, wA.x, a4); a5 = fma2(hv.y, wA.y, a5);
                    a6 = fma2(hv.y, wB.x, a6); a7 = fma2(hv.y, wB.y, a7);
                    wp += W2S; hp += H2S;
                }
                float* pb = p_sm + kg * 1024 + b0 * 64 + 4 * jq;
                float4 o;
                upk2(a0, o.x, o.y); upk2(a1, o.z, o.w); *(float4*)pb = o;
                upk2(a2, o.x, o.y); upk2(a3, o.z, o.w); *(float4*)(pb + 32) = o;
                upk2(a4, o.x, o.y); upk2(a5, o.z, o.w); *(float4*)(pb + 64) = o;
                upk2(a6, o.x, o.y); upk2(a7, o.z, o.w); *(float4*)(pb + 96) = o;
            }

            // ---- wait for attention m_t of this step ----
            if (tx == 0) {
                volatile unsigned* fl = (volatile unsigned*)d_aflag;
                while (fl[i] < (unsigned)NATT_CTA) { }
            }
            __syncthreads();   // partials complete + flag visible

            // ---- reduce 4 partials + input proj -> g_sm ----
            {
                float4 s = gpre;
#pragma unroll
                for (int kk = 0; kk < 4; kk++) {
                    float4 p = *(const float4*)&p_sm[kk * 1024 + bl * 64 + j0];
                    s.x += p.x; s.y += p.y; s.z += p.z; s.w += p.w;
                }
                *(float4*)&g_sm[bl * 68 + j0] = s;
            }
            __syncthreads();

            // ---- LSTM cell: (b = bg*16+bl, h = h0+hi) ----
            {
                float gi = g_sm[bl * 68 + hi];
                float gf = g_sm[bl * 68 + 16 + hi];
                float gg = g_sm[bl * 68 + 32 + hi];
                float go = g_sm[bl * 68 + 48 + hi];
                size_t off = (size_t)(bg * 16 + bl) * H_ + h0 + hi;
                float mt = __ldcg(d_mseq + (size_t)i * BH + off);

                float cn = sigf(gf) * cstate + sigf(gi) * tanhf(gg);
                float hn = sigf(go) * tanhf(cn);
                cstate = cn;
                float ho = hn + mt;
                d_mem[(size_t)(i + 1) * BH + off] = ho;

                float part = tanhf(ho) * wt2v;
#pragma unroll
                for (int o = 8; o > 0; o >>= 1) part += __shfl_xor_sync(0xffffffffu, part, o);
                if ((lane & 15) == 0)
                    atomicAdd(&d_s2[(bg * 16 + bl) * (T_ + 1) + (i + 1)], part);
            }

            gsync(i, NCTA);
        }
    } else {
        // ---------------- attention CTAs: warp per batch (R6) ----------------
        int b = (g - NGEMM) * 8 + wrp;
        for (int i = 0; i < T_; ++i) {
            int n = i + 1;
            float v[8];
            float mn = INFINITY;
#pragma unroll
            for (int r = 0; r < 8; r++) {
                int t = lane + 32 * r;
                if (t < n) {
                    float s = __ldcg(d_s2 + b * (T_ + 1) + t);
                    v[r] = s;
                    mn = fminf(mn, s);
                } else {
                    v[r] = -INFINITY;
                }
            }
#pragma unroll
            for (int o = 16; o > 0; o >>= 1) mn = fminf(mn, __shfl_xor_sync(0xffffffffu, mn, o));
            float topv[5]; int topt[5];
#pragma unroll
            for (int k5 = 0; k5 < 5; k5++) {
                float bv = -INFINITY; int bt = 1 << 30;
#pragma unroll
                for (int r = 0; r < 8; r++) {
                    int t = lane + 32 * r;
                    if (v[r] > bv) { bv = v[r]; bt = t; }
                }
#pragma unroll
                for (int o = 16; o > 0; o >>= 1) {
                    float ov = __shfl_xor_sync(0xffffffffu, bv, o);
                    int   ot = __shfl_xor_sync(0xffffffffu, bt, o);
                    if (ov > bv || (ov == bv && ot < bt)) { bv = ov; bt = ot; }
                }
                topv[k5] = bv; topt[k5] = bt;
                int rr = bt >> 5;
                if ((bt & 31) == lane && rr >= 0 && rr < 8) v[rr] = -INFINITY;
            }
            float delta = ((n <= 5) ? mn : topv[4]) + 1e-7f;
            float wk[5]; float sum = 0.f;
#pragma unroll
            for (int k5 = 0; k5 < 5; k5++) { wk[k5] = fmaxf(topv[k5] - delta, 0.f); sum += wk[k5]; }
            float inv = 1.f / (sum + 1e-7f);
            float acc[16];
#pragma unroll
            for (int r = 0; r < 16; r++) acc[r] = 0.f;
#pragma unroll
            for (int k5 = 0; k5 < 5; k5++) {
                float wv = wk[k5] * inv;
                if (wv > 0.f) {
                    const float* rowp = d_mem + (size_t)topt[k5] * BH + (size_t)b * H_;
#pragma unroll
                    for (int r = 0; r < 16; r++) acc[r] = fmaf(wv, __ldg(rowp + lane + 32 * r), acc[r]);
                }
            }
            float* mrow = d_mseq + (size_t)i * BH + (size_t)b * H_;
#pragma unroll
            for (int r = 0; r < 16; r++) mrow[lane + 32 * r] = acc[r];

            __threadfence();
            __syncthreads();
            if (tx == 0) atomicAdd(&d_aflag[i], 1u);

            gsync(i, NCTA);
        }
    }
}

// ---------------- K3: out = [h_seq | m_seq] @ fc_w^T + fc_b (R12 version) ----------------
__global__ void __launch_bounds__(256) fc_final_kernel(const float* __restrict__ fcw,
                                                       const float* __restrict__ fcb,
                                                       float* __restrict__ out) {
    __shared__ __align__(16) float a_s[16][36];   // [k][m] pad to 36
    __shared__ __align__(16) float b_s[16][64];   // [k][n]
    int tx = threadIdx.x;
    int m0 = blockIdx.x * 32;
    int tm = tx >> 5, tn = tx & 31;
    float acc[4][2];
#pragma unroll
    for (int r = 0; r < 4; r++) { acc[r][0] = 0.f; acc[r][1] = 0.f; }

    int arow = tx >> 2, aqd = tx & 3;
    int am = m0 + (arow & 31), at = am >> 6, ab = am & 63;
    int brow = tx >> 2, bqd = tx & 3;

    for (int k0 = 0; k0 < 2 * H_; k0 += 16) {
        if (tx < 128) {
            int k = k0 + aqd * 4;
            const float* src = (k < H_)
                ? (d_mem + ((size_t)(at + 1) * B_ + ab) * H_ + k)
                : (d_mseq + ((size_t)at * B_ + ab) * H_ + (k - H_));
            float4 av = *(const float4*)src;
            a_s[aqd*4+0][arow] = av.x; a_s[aqd*4+1][arow] = av.y;
            a_s[aqd*4+2][arow] = av.z; a_s[aqd*4+3][arow] = av.w;
        }
        {
            float4 bv = *(const float4*)(fcw + (size_t)brow * (2 * H_) + k0 + bqd * 4);
            b_s[bqd*4+0][brow] = bv.x; b_s[bqd*4+1][brow] = bv.y;
            b_s[bqd*4+2][brow] = bv.z; b_s[bqd*4+3][brow] = bv.w;
        }
        __syncthreads();
#pragma unroll
        for (int k = 0; k < 16; k++) {
            float4 a = *(const float4*)&a_s[k][tm * 4];
            float2 bb = *(const float2*)&b_s[k][tn * 2];
            acc[0][0] = fmaf(a.x, bb.x, acc[0][0]); acc[0][1] = fmaf(a.x, bb.y, acc[0][1]);
            acc[1][0] = fmaf(a.y, bb.x, acc[1][0]); acc[1][1] = fmaf(a.y, bb.y, acc[1][1]);
            acc[2][0] = fmaf(a.z, bb.x, acc[2][0]); acc[2][1] = fmaf(a.z, bb.y, acc[2][1]);
            acc[3][0] = fmaf(a.w, bb.x, acc[3][0]); acc[3][1] = fmaf(a.w, bb.y, acc[3][1]);
        }
        __syncthreads();
    }
    float b0f = __ldg(fcb + tn * 2), b1f = __ldg(fcb + tn * 2 + 1);
#pragma unroll
    for (int r = 0; r < 4; r++) {
        size_t mm = (size_t)(m0 + tm * 4 + r);
        float2 o = make_float2(acc[r][0] + b0f, acc[r][1] + b1f);
        *(float2*)(out + mm * C_ + tn * 2) = o;
    }
}

// ---------------- launch ----------------
extern "C" void kernel_launch(void* const* d_in, const int* in_sizes, int n_in,
                              void* d_out, int out_size) {
    const float* x    = (const float*)d_in[0];
    const float* W_ih = (const float*)d_in[1];
    const float* W_hh = (const float*)d_in[2];
    const float* b_ih = (const float*)d_in[3];
    const float* b_hh = (const float*)d_in[4];
    const float* w_t  = (const float*)d_in[5];
    const float* fc_w = (const float*)d_in[6];
    const float* fc_b = (const float*)d_in[7];
    float* out = (float*)d_out;

    static int smem_set = 0;
    if (!smem_set) {
        cudaFuncSetAttribute(lstm_persistent,
                             cudaFuncAttributeMaxDynamicSharedMemorySize, SMEM_BYTES);
        smem_set = 1;
    }

    // ncu profiles launch #4 -> keep gemm_ih there to verify the K1 v2 prediction.
    reset_kernel<<<64, 512>>>();
    noop_kernel<<<1, 1>>>();
    noop_kernel<<<1, 1>>>();
    gemm_ih_kernel<<<dim3(G4H / 128, (T_ * B_) / 128), 256>>>(x, W_ih, b_ih, b_hh);
    lstm_persistent<<<NCTA, 256, SMEM_BYTES>>>(W_hh, w_t);
    fc_final_kernel<<<(T_ * B_) / 32, 256>>>(fc_w, fc_b, out);
}

// round 16
// speedup vs baseline: 1.7077x; 1.0147x over previous
#include <cuda_runtime.h>
#include <math.h>
#include <stdint.h>

#define T_   256
#define B_   64
#define I_   256
#define H_   512
#define C_   64
#define G4H  2048
#define BH   (B_*H_)      // 32768
#define NCTA 136
#define NGEMM 128
#define NATT_CTA 8
#define NSYNC 256

// lstm smem (floats): w2 [k][jp-pairs] stride 68, h2dup [k][b-dup] stride 36,
// partials [kg][b][j] 4*1024. g_sm (16x68) aliases h2 start.
#define W2S 68
#define H2S 36
#define W2_ELE (512 * W2S)        // 34816
#define H2_ELE (512 * H2S)        // 18432
#define PT_ELE (4 * 1024)         // 4096
#define SMEM_FLOATS (W2_ELE + H2_ELE + PT_ELE)
#define SMEM_BYTES  (SMEM_FLOATS * 4)   // 229376 B

// ---------------- static device scratch ----------------
__device__ float    d_G[(size_t)T_ * B_ * G4H];
__device__ float    d_mem[(size_t)(T_ + 1) * BH];   // mem rows; mem[i+1] = h_out[i]
__device__ float    d_mseq[(size_t)T_ * BH];        // m_t per step
__device__ float    d_s2[B_ * (T_ + 1)];            // cached memory scores, [b][t]
__device__ unsigned d_bar[NSYNC];
__device__ unsigned d_aflag[NSYNC];

__device__ __forceinline__ float sigf(float x) { return 1.f / (1.f + __expf(-x)); }

__device__ __forceinline__ unsigned long long pk2(float x, float y) {
    unsigned long long r;
    asm("mov.b64 %0, {%1, %2};" : "=l"(r) : "f"(x), "f"(y));
    return r;
}
__device__ __forceinline__ void upk2(unsigned long long v, float& x, float& y) {
    asm("mov.b64 {%0, %1}, %2;" : "=f"(x), "=f"(y) : "l"(v));
}
__device__ __forceinline__ unsigned long long fma2(unsigned long long a,
                                                   unsigned long long b,
                                                   unsigned long long c) {
    unsigned long long d;
    asm("fma.rn.f32x2 %0, %1, %2, %3;" : "=l"(d) : "l"(a), "l"(b), "l"(c));
    return d;
}

// release/acquire grid barrier; fence+arrive+spin by thread 0 only
__device__ __forceinline__ void gsync(int slot, unsigned nct) {
    __syncthreads();
    if (threadIdx.x == 0) {
        __threadfence();
        atomicAdd(&d_bar[slot], 1u);
        while (*((volatile unsigned*)&d_bar[slot]) < nct) { }
        __threadfence();
    }
    __syncthreads();
}

__global__ void noop_kernel() {}

// ---------------- reset (R6) ----------------
__global__ void reset_kernel() {
    int id = blockIdx.x * blockDim.x + threadIdx.x;   // 32768 threads
    d_mem[id] = 0.f;
    if (id < B_ * (T_ + 1)) d_s2[id] = 0.f;
    if (id < NSYNC) { d_bar[id] = 0u; d_aflag[id] = 0u; }
}

// ---------------- K1 v3: G = x @ W_ih^T + (b_ih + b_hh), FFMA2 compute ----------------
// 128x128 tile, 256 threads, 8x8 micro-tile as 8m x 4 n-pairs of f32x2.
// b pairs read directly as packed 64-bit from smem; a dup'd in registers (8 movs/k).
#define K1_AS 132
__global__ void __launch_bounds__(256) gemm_ih_kernel(const float* __restrict__ X,
                                                      const float* __restrict__ Wih,
                                                      const float* __restrict__ bih,
                                                      const float* __restrict__ bhh) {
    __shared__ __align__(16) float a_s[8][K1_AS];   // [k][m], 128 + pad
    __shared__ __align__(16) float b_s[8][K1_AS];   // [k][n]
    int tx = threadIdx.x;
    int m0 = blockIdx.y * 128, n0 = blockIdx.x * 128;
    int tm = tx & 15, tn = tx >> 4;                  // 16 x 16 thread grid
    int lrow = tx >> 1, lkq = tx & 1;                // loader: 128 rows x 2 k-quads

    unsigned long long acc2[8][4];                   // [m][n-pair]
#pragma unroll
    for (int r = 0; r < 8; r++)
#pragma unroll
        for (int c = 0; c < 4; c++) acc2[r][c] = 0ull;

    for (int k0 = 0; k0 < I_; k0 += 8) {
        float4 av = *(const float4*)(X + (size_t)(m0 + lrow) * I_ + k0 + lkq * 4);
        a_s[lkq*4+0][lrow] = av.x; a_s[lkq*4+1][lrow] = av.y;
        a_s[lkq*4+2][lrow] = av.z; a_s[lkq*4+3][lrow] = av.w;
        float4 bv = *(const float4*)(Wih + (size_t)(n0 + lrow) * I_ + k0 + lkq * 4);
        b_s[lkq*4+0][lrow] = bv.x; b_s[lkq*4+1][lrow] = bv.y;
        b_s[lkq*4+2][lrow] = bv.z; b_s[lkq*4+3][lrow] = bv.w;
        __syncthreads();
#pragma unroll
        for (int k = 0; k < 8; k++) {
            float4 aA = *(const float4*)&a_s[k][tm * 8];
            float4 aB = *(const float4*)&a_s[k][tm * 8 + 4];
            ulonglong2 bP = *(const ulonglong2*)&b_s[k][tn * 8];      // pairs (n0,n1),(n2,n3)
            ulonglong2 bQ = *(const ulonglong2*)&b_s[k][tn * 8 + 4];  // pairs (n4,n5),(n6,n7)
            unsigned long long a2r[8];
            a2r[0] = pk2(aA.x, aA.x); a2r[1] = pk2(aA.y, aA.y);
            a2r[2] = pk2(aA.z, aA.z); a2r[3] = pk2(aA.w, aA.w);
            a2r[4] = pk2(aB.x, aB.x); a2r[5] = pk2(aB.y, aB.y);
            a2r[6] = pk2(aB.z, aB.z); a2r[7] = pk2(aB.w, aB.w);
#pragma unroll
            for (int r = 0; r < 8; r++) {
                acc2[r][0] = fma2(a2r[r], bP.x, acc2[r][0]);
                acc2[r][1] = fma2(a2r[r], bP.y, acc2[r][1]);
                acc2[r][2] = fma2(a2r[r], bQ.x, acc2[r][2]);
                acc2[r][3] = fma2(a2r[r], bQ.y, acc2[r][3]);
            }
        }
        __syncthreads();
    }
    float bias[8];
#pragma unroll
    for (int c = 0; c < 8; c++) {
        int n = n0 + tn * 8 + c;
        bias[c] = __ldg(bih + n) + __ldg(bhh + n);
    }
#pragma unroll
    for (int r = 0; r < 8; r++) {
        size_t m = (size_t)(m0 + tm * 8 + r);
        float* dst = d_G + m * G4H + n0 + tn * 8;
        float4 o0, o1;
        upk2(acc2[r][0], o0.x, o0.y);
        upk2(acc2[r][1], o0.z, o0.w);
        upk2(acc2[r][2], o1.x, o1.y);
        upk2(acc2[r][3], o1.z, o1.w);
        o0.x += bias[0]; o0.y += bias[1]; o0.z += bias[2]; o0.w += bias[3];
        o1.x += bias[4]; o1.y += bias[5]; o1.z += bias[6]; o1.w += bias[7];
        *(float4*)dst = o0;
        *(float4*)(dst + 4) = o1;
    }
}

// ---------------- K2: fused persistent recurrent kernel (R6, byte-identical) ----------------
__global__ void __launch_bounds__(256, 1) lstm_persistent(const float* __restrict__ W_hh,
                                                          const float* __restrict__ w_t) {
    extern __shared__ __align__(16) float smem[];
    float* w2f  = smem;                     // [k][2*jp] pairs, stride W2S
    float* h2f  = smem + W2_ELE;            // [k][2*b] dup'd pairs, stride H2S
    float* p_sm = smem + W2_ELE + H2_ELE;   // partials [kg][b][j]
    float* g_sm = h2f;                      // gates [b][j] stride 68 (aliases h2; sync-ordered)

    int g = blockIdx.x, tx = threadIdx.x;
    int wrp = tx >> 5, lane = tx & 31;

    if (g < NGEMM) {
        int jg = g >> 2, bg = g & 3;
        int h0 = jg * 16;

        // ---- stage W pairs once ----
#pragma unroll
        for (int q2 = 0; q2 < 64; q2++) {
            int idx = q2 * 256 + tx;
            int jp = idx >> 9, k = idx & 511;
            int jj0 = 2 * jp, jj1 = 2 * jp + 1;
            int r0 = (jj0 >> 4) * H_ + h0 + (jj0 & 15);
            int r1 = (jj1 >> 4) * H_ + h0 + (jj1 & 15);
            float2 v;
            v.x = __ldg(W_hh + (size_t)r0 * H_ + k);
            v.y = __ldg(W_hh + (size_t)r1 * H_ + k);
            *(float2*)&w2f[k * W2S + 2 * jp] = v;
        }
        __syncthreads();

        int kg = wrp & 3, half = wrp >> 2;
        int bq = lane >> 3, jq = lane & 7;
        int b0 = half * 8 + bq * 2;

        int bl = tx >> 4;
        int j0 = (tx & 15) * 4;
        int hi = tx & 15;
        const float* gsrc = d_G + ((size_t)bg * 16 + bl) * G4H
                            + (size_t)(j0 >> 4) * H_ + h0 + (j0 & 15);
        float wt2v = __ldg(w_t + H_ + h0 + hi);
        float cstate = 0.f;

        for (int i = 0; i < T_; ++i) {
            float4 gpre = __ldcg((const float4*)(gsrc + (size_t)i * B_ * G4H));

            // ---- stage h2 dup'd from d_mem[i] ----
            const float* hrow = d_mem + (size_t)i * BH + (size_t)bg * 16 * H_;
#pragma unroll
            for (int q2 = 0; q2 < 8; q2++) {
                int it = q2 * 256 + tx;
                int b = it & 15, kq = it >> 4;
                float4 v = __ldcg((const float4*)(hrow + (size_t)b * H_ + kq * 4));
                *(float2*)&h2f[(4*kq+0) * H2S + 2*b] = make_float2(v.x, v.x);
                *(float2*)&h2f[(4*kq+1) * H2S + 2*b] = make_float2(v.y, v.y);
                *(float2*)&h2f[(4*kq+2) * H2S + 2*b] = make_float2(v.z, v.z);
                *(float2*)&h2f[(4*kq+3) * H2S + 2*b] = make_float2(v.w, v.w);
            }
            __syncthreads();

            // ---- FFMA2 k-loop: 128 k per warp, 2b x 8j per lane ----
            {
                unsigned long long a0=0,a1=0,a2=0,a3=0,a4=0,a5=0,a6=0,a7=0;
                const float* wp = w2f + (size_t)(kg * 128) * W2S + 4 * jq;
                const float* hp = h2f + (size_t)(kg * 128) * H2S + 2 * b0;
#pragma unroll 8
                for (int k = 0; k < 128; k++) {
                    ulonglong2 hv = *(const ulonglong2*)hp;
                    ulonglong2 wA = *(const ulonglong2*)wp;
                    ulonglong2 wB = *(const ulonglong2*)(wp + 32);
                    a0 = fma2(hv.x, wA.x, a0); a1 = fma2(hv.x, wA.y, a1);
                    a2 = fma2(hv.x, wB.x, a2); a3 = fma2(hv.x, wB.y, a3);
                    a4 = fma2(hv.y, wA.x, a4); a5 = fma2(hv.y, wA.y, a5);
                    a6 = fma2(hv.y, wB.x, a6); a7 = fma2(hv.y, wB.y, a7);
                    wp += W2S; hp += H2S;
                }
                float* pb = p_sm + kg * 1024 + b0 * 64 + 4 * jq;
                float4 o;
                upk2(a0, o.x, o.y); upk2(a1, o.z, o.w); *(float4*)pb = o;
                upk2(a2, o.x, o.y); upk2(a3, o.z, o.w); *(float4*)(pb + 32) = o;
                upk2(a4, o.x, o.y); upk2(a5, o.z, o.w); *(float4*)(pb + 64) = o;
                upk2(a6, o.x, o.y); upk2(a7, o.z, o.w); *(float4*)(pb + 96) = o;
            }

            // ---- wait for attention m_t of this step ----
            if (tx == 0) {
                volatile unsigned* fl = (volatile unsigned*)d_aflag;
                while (fl[i] < (unsigned)NATT_CTA) { }
            }
            __syncthreads();   // partials complete + flag visible

            // ---- reduce 4 partials + input proj -> g_sm ----
            {
                float4 s = gpre;
#pragma unroll
                for (int kk = 0; kk < 4; kk++) {
                    float4 p = *(const float4*)&p_sm[kk * 1024 + bl * 64 + j0];
                    s.x += p.x; s.y += p.y; s.z += p.z; s.w += p.w;
                }
                *(float4*)&g_sm[bl * 68 + j0] = s;
            }
            __syncthreads();

            // ---- LSTM cell: (b = bg*16+bl, h = h0+hi) ----
            {
                float gi = g_sm[bl * 68 + hi];
                float gf = g_sm[bl * 68 + 16 + hi];
                float gg = g_sm[bl * 68 + 32 + hi];
                float go = g_sm[bl * 68 + 48 + hi];
                size_t off = (size_t)(bg * 16 + bl) * H_ + h0 + hi;
                float mt = __ldcg(d_mseq + (size_t)i * BH + off);

                float cn = sigf(gf) * cstate + sigf(gi) * tanhf(gg);
                float hn = sigf(go) * tanhf(cn);
                cstate = cn;
                float ho = hn + mt;
                d_mem[(size_t)(i + 1) * BH + off] = ho;

                float part = tanhf(ho) * wt2v;
#pragma unroll
                for (int o = 8; o > 0; o >>= 1) part += __shfl_xor_sync(0xffffffffu, part, o);
                if ((lane & 15) == 0)
                    atomicAdd(&d_s2[(bg * 16 + bl) * (T_ + 1) + (i + 1)], part);
            }

            gsync(i, NCTA);
        }
    } else {
        // ---------------- attention CTAs: warp per batch (R6) ----------------
        int b = (g - NGEMM) * 8 + wrp;
        for (int i = 0; i < T_; ++i) {
            int n = i + 1;
            float v[8];
            float mn = INFINITY;
#pragma unroll
            for (int r = 0; r < 8; r++) {
                int t = lane + 32 * r;
                if (t < n) {
                    float s = __ldcg(d_s2 + b * (T_ + 1) + t);
                    v[r] = s;
                    mn = fminf(mn, s);
                } else {
                    v[r] = -INFINITY;
                }
            }
#pragma unroll
            for (int o = 16; o > 0; o >>= 1) mn = fminf(mn, __shfl_xor_sync(0xffffffffu, mn, o));
            float topv[5]; int topt[5];
#pragma unroll
            for (int k5 = 0; k5 < 5; k5++) {
                float bv = -INFINITY; int bt = 1 << 30;
#pragma unroll
                for (int r = 0; r < 8; r++) {
                    int t = lane + 32 * r;
                    if (v[r] > bv) { bv = v[r]; bt = t; }
                }
#pragma unroll
                for (int o = 16; o > 0; o >>= 1) {
                    float ov = __shfl_xor_sync(0xffffffffu, bv, o);
                    int   ot = __shfl_xor_sync(0xffffffffu, bt, o);
                    if (ov > bv || (ov == bv && ot < bt)) { bv = ov; bt = ot; }
                }
                topv[k5] = bv; topt[k5] = bt;
                int rr = bt >> 5;
                if ((bt & 31) == lane && rr >= 0 && rr < 8) v[rr] = -INFINITY;
            }
            float delta = ((n <= 5) ? mn : topv[4]) + 1e-7f;
            float wk[5]; float sum = 0.f;
#pragma unroll
            for (int k5 = 0; k5 < 5; k5++) { wk[k5] = fmaxf(topv[k5] - delta, 0.f); sum += wk[k5]; }
            float inv = 1.f / (sum + 1e-7f);
            float acc[16];
#pragma unroll
            for (int r = 0; r < 16; r++) acc[r] = 0.f;
#pragma unroll
            for (int k5 = 0; k5 < 5; k5++) {
                float wv = wk[k5] * inv;
                if (wv > 0.f) {
                    const float* rowp = d_mem + (size_t)topt[k5] * BH + (size_t)b * H_;
#pragma unroll
                    for (int r = 0; r < 16; r++) acc[r] = fmaf(wv, __ldg(rowp + lane + 32 * r), acc[r]);
                }
            }
            float* mrow = d_mseq + (size_t)i * BH + (size_t)b * H_;
#pragma unroll
            for (int r = 0; r < 16; r++) mrow[lane + 32 * r] = acc[r];

            __threadfence();
            __syncthreads();
            if (tx == 0) atomicAdd(&d_aflag[i], 1u);

            gsync(i, NCTA);
        }
    }
}

// ---------------- K3: out = [h_seq | m_seq] @ fc_w^T + fc_b (R12 version) ----------------
__global__ void __launch_bounds__(256) fc_final_kernel(const float* __restrict__ fcw,
                                                       const float* __restrict__ fcb,
                                                       float* __restrict__ out) {
    __shared__ __align__(16) float a_s[16][36];   // [k][m] pad to 36
    __shared__ __align__(16) float b_s[16][64];   // [k][n]
    int tx = threadIdx.x;
    int m0 = blockIdx.x * 32;
    int tm = tx >> 5, tn = tx & 31;
    float acc[4][2];
#pragma unroll
    for (int r = 0; r < 4; r++) { acc[r][0] = 0.f; acc[r][1] = 0.f; }

    int arow = tx >> 2, aqd = tx & 3;
    int am = m0 + (arow & 31), at = am >> 6, ab = am & 63;
    int brow = tx >> 2, bqd = tx & 3;

    for (int k0 = 0; k0 < 2 * H_; k0 += 16) {
        if (tx < 128) {
            int k = k0 + aqd * 4;
            const float* src = (k < H_)
                ? (d_mem + ((size_t)(at + 1) * B_ + ab) * H_ + k)
                : (d_mseq + ((size_t)at * B_ + ab) * H_ + (k - H_));
            float4 av = *(const float4*)src;
            a_s[aqd*4+0][arow] = av.x; a_s[aqd*4+1][arow] = av.y;
            a_s[aqd*4+2][arow] = av.z; a_s[aqd*4+3][arow] = av.w;
        }
        {
            float4 bv = *(const float4*)(fcw + (size_t)brow * (2 * H_) + k0 + bqd * 4);
            b_s[bqd*4+0][brow] = bv.x; b_s[bqd*4+1][brow] = bv.y;
            b_s[bqd*4+2][brow] = bv.z; b_s[bqd*4+3][brow] = bv.w;
        }
        __syncthreads();
#pragma unroll
        for (int k = 0; k < 16; k++) {
            float4 a = *(const float4*)&a_s[k][tm * 4];
            float2 bb = *(const float2*)&b_s[k][tn * 2];
            acc[0][0] = fmaf(a.x, bb.x, acc[0][0]); acc[0][1] = fmaf(a.x, bb.y, acc[0][1]);
            acc[1][0] = fmaf(a.y, bb.x, acc[1][0]); acc[1][1] = fmaf(a.y, bb.y, acc[1][1]);
            acc[2][0] = fmaf(a.z, bb.x, acc[2][0]); acc[2][1] = fmaf(a.z, bb.y, acc[2][1]);
            acc[3][0] = fmaf(a.w, bb.x, acc[3][0]); acc[3][1] = fmaf(a.w, bb.y, acc[3][1]);
        }
        __syncthreads();
    }
    float b0f = __ldg(fcb + tn * 2), b1f = __ldg(fcb + tn * 2 + 1);
#pragma unroll
    for (int r = 0; r < 4; r++) {
        size_t mm = (size_t)(m0 + tm * 4 + r);
        float2 o = make_float2(acc[r][0] + b0f, acc[r][1] + b1f);
        *(float2*)(out + mm * C_ + tn * 2) = o;
    }
}

// ---------------- launch ----------------
extern "C" void kernel_launch(void* const* d_in, const int* in_sizes, int n_in,
                              void* d_out, int out_size) {
    const float* x    = (const float*)d_in[0];
    const float* W_ih = (const float*)d_in[1];
    const float* W_hh = (const float*)d_in[2];
    const float* b_ih = (const float*)d_in[3];
    const float* b_hh = (const float*)d_in[4];
    const float* w_t  = (const float*)d_in[5];
    const float* fc_w = (const float*)d_in[6];
    const float* fc_b = (const float*)d_in[7];
    float* out = (float*)d_out;

    static int smem_set = 0;
    if (!smem_set) {
        cudaFuncSetAttribute(lstm_persistent,
                             cudaFuncAttributeMaxDynamicSharedMemorySize, SMEM_BYTES);
        smem_set = 1;
    }

    // ncu profiles launch #4 -> keep gemm_ih there to adjudicate FFMA2-in-K1.
    reset_kernel<<<64, 512>>>();
    noop_kernel<<<1, 1>>>();
    noop_kernel<<<1, 1>>>();
    gemm_ih_kernel<<<dim3(G4H / 128, (T_ * B_) / 128), 256>>>(x, W_ih, b_ih, b_hh);
    lstm_persistent<<<NCTA, 256, SMEM_BYTES>>>(W_hh, w_t);
    fc_final_kernel<<<(T_ * B_) / 32, 256>>>(fc_w, fc_b, out);
}